// round 1
// baseline (speedup 1.0000x reference)
#include <cuda_runtime.h>
#include <cuda_bf16.h>
#include <cstdio>

// ---------------------------------------------------------------------------
// Scratch pool: 5 slots x 9,437,184 floats (largest activation = 8x128x96x96)
// ---------------------------------------------------------------------------
#define SLOT_ELEMS 9437184
__device__ float g_pool[5ull * SLOT_ELEMS];

// Flags for conv kernels
#define F_BIAS  1
#define F_RELU  2
#define F_NEG   4
#define F_TRANS 8

// ---------------------------------------------------------------------------
// Block reduction
// ---------------------------------------------------------------------------
__device__ __forceinline__ float blockReduceSum(float v) {
    __shared__ float sb[32];
    __syncthreads();  // protect sb reuse across consecutive calls
    int lane = threadIdx.x & 31, w = threadIdx.x >> 5;
#pragma unroll
    for (int o = 16; o > 0; o >>= 1) v += __shfl_down_sync(0xffffffffu, v, o);
    if (lane == 0) sb[w] = v;
    __syncthreads();
    int nw = blockDim.x >> 5;
    v = (threadIdx.x < nw) ? sb[threadIdx.x] : 0.f;
    if (w == 0) {
#pragma unroll
        for (int o = 16; o > 0; o >>= 1) v += __shfl_down_sync(0xffffffffu, v, o);
    }
    return v;  // valid on thread 0
}

// ---------------------------------------------------------------------------
// Direct 3x3 conv, pad=1, stride=1.
// Block: BX x BY threads; each thread computes a 2x2 pixel patch for 4
// consecutive output channels. Output tile = (2BX) x (2BY).
// flags: F_BIAS add bias, F_RELU relu, F_NEG negate, F_TRANS use
//        W[ci][co][2-kh][2-kw] (transposed-conv weight view).
// ---------------------------------------------------------------------------
template <int BX, int BY>
__global__ void conv3x3_kernel(const float* __restrict__ in,
                               const float* __restrict__ wt,
                               const float* __restrict__ bias,
                               float* __restrict__ out,
                               int Cin, int Cout, int H, int W,
                               int tilesX, int flags) {
    constexpr int TX = 2 * BX, TY = 2 * BY;
    constexpr int SW = TX + 2, SH = TY + 2;
    __shared__ float s_in[SH * SW];
    __shared__ float s_w[36];

    const int n    = blockIdx.z;
    const int coB  = blockIdx.y * 4;
    const int tile = blockIdx.x;
    const int tX = tile % tilesX, tY = tile / tilesX;
    const int wbase = tX * TX - 1, hbase = tY * TY - 1;
    const int tx = threadIdx.x, ty = threadIdx.y;
    const int tid = ty * BX + tx;
    constexpr int NT = BX * BY;
    const bool trans = (flags & F_TRANS) != 0;

    float acc[4][4];
#pragma unroll
    for (int a = 0; a < 4; a++)
#pragma unroll
        for (int b = 0; b < 4; b++) acc[a][b] = 0.f;

    for (int ci = 0; ci < Cin; ci++) {
        const float* ip = in + ((size_t)(n * Cin + ci)) * H * W;
        for (int idx = tid; idx < SH * SW; idx += NT) {
            int r = idx / SW, c = idx % SW;
            int gh = hbase + r, gw = wbase + c;
            float v = 0.f;
            if (gh >= 0 && gh < H && gw >= 0 && gw < W) v = ip[gh * W + gw];
            s_in[idx] = v;
        }
        if (tid < 36) {
            int col = tid / 9, k = tid % 9, kh = k / 3, kw = k % 3;
            int co = coB + col;
            int widx = trans
                ? ((ci * Cout + co) * 3 + (2 - kh)) * 3 + (2 - kw)
                : ((co * Cin + ci) * 3 + kh) * 3 + kw;
            s_w[tid] = wt[widx];
        }
        __syncthreads();

        float rr[4][4];
#pragma unroll
        for (int r = 0; r < 4; r++)
#pragma unroll
            for (int c = 0; c < 4; c++)
                rr[r][c] = s_in[(2 * ty + r) * SW + 2 * tx + c];

#pragma unroll
        for (int co = 0; co < 4; co++) {
#pragma unroll
            for (int kh = 0; kh < 3; kh++)
#pragma unroll
                for (int kw = 0; kw < 3; kw++) {
                    float wv = s_w[co * 9 + kh * 3 + kw];
                    acc[co][0] += rr[kh][kw] * wv;
                    acc[co][1] += rr[kh][kw + 1] * wv;
                    acc[co][2] += rr[kh + 1][kw] * wv;
                    acc[co][3] += rr[kh + 1][kw + 1] * wv;
                }
        }
        __syncthreads();
    }

#pragma unroll
    for (int co = 0; co < 4; co++) {
        int co_g = coB + co;
        float bv = (flags & F_BIAS) ? bias[co_g] : 0.f;
#pragma unroll
        for (int oy = 0; oy < 2; oy++)
#pragma unroll
            for (int ox = 0; ox < 2; ox++) {
                int h = hbase + 1 + 2 * ty + oy;
                int w = wbase + 1 + 2 * tx + ox;
                if (h < H && w < W) {
                    float v = acc[co][oy * 2 + ox] + bv;
                    if (flags & F_RELU) v = fmaxf(v, 0.f);
                    if (flags & F_NEG) v = -v;
                    out[(((size_t)n * Cout + co_g) * H + h) * W + w] = v;
                }
            }
    }
}

// ---------------------------------------------------------------------------
// Instance norm over H*W per (n,c), in place. gamma/beta optional, relu opt.
// grid: (C, N), block 256
// ---------------------------------------------------------------------------
__global__ void instnorm_kernel(float* __restrict__ x,
                                const float* __restrict__ gamma,
                                const float* __restrict__ beta,
                                int HW, int relu) {
    int C = gridDim.x;
    int c = blockIdx.x, n = blockIdx.y;
    float* p = x + (size_t)(n * C + c) * HW;
    float s = 0.f, s2 = 0.f;
    for (int i = threadIdx.x; i < HW; i += blockDim.x) {
        float v = p[i];
        s += v;
        s2 += v * v;
    }
    float ts = blockReduceSum(s);
    float ts2 = blockReduceSum(s2);
    __shared__ float res[2];
    if (threadIdx.x == 0) {
        float mu = ts / HW;
        float var = ts2 / HW - mu * mu;
        res[0] = mu;
        res[1] = rsqrtf(var + 1e-5f);
    }
    __syncthreads();
    float mu = res[0], inv = res[1];
    float sc = inv, sh = -mu * inv;
    if (gamma) {
        float g = gamma[c], b = beta[c];
        sc = inv * g;
        sh = b - mu * inv * g;
    }
    for (int i = threadIdx.x; i < HW; i += blockDim.x) {
        float v = p[i] * sc + sh;
        if (relu) v = fmaxf(v, 0.f);
        p[i] = v;
    }
}

// ---------------------------------------------------------------------------
// RK4 combining kernel.
// stage 1: acc=k;      tin=y+0.5dt*k
// stage 2: acc+=2k;    tin=y+0.5dt*k
// stage 3: acc+=2k;    tin=y+dt*k
// stage 4: y+=dt/6*(acc+k)
// ---------------------------------------------------------------------------
__global__ void rk_update_kernel(float* __restrict__ y, float* __restrict__ acc,
                                 float* __restrict__ tin, const float* __restrict__ k,
                                 long n, int stage, float dt) {
    long i = (long)blockIdx.x * blockDim.x + threadIdx.x;
    if (i >= n) return;
    float kv = k[i];
    if (stage == 1) {
        acc[i] = kv;
        tin[i] = y[i] + 0.5f * dt * kv;
    } else if (stage == 2) {
        acc[i] += 2.f * kv;
        tin[i] = y[i] + 0.5f * dt * kv;
    } else if (stage == 3) {
        acc[i] += 2.f * kv;
        tin[i] = y[i] + dt * kv;
    } else {
        y[i] += (dt / 6.f) * (acc[i] + kv);
    }
}

// ---------------------------------------------------------------------------
// 1x1 conv + bias. grid (pxTiles, Cout/8, N), block 256. Cin <= 128.
// ---------------------------------------------------------------------------
__global__ void conv1x1_kernel(const float* __restrict__ in,
                               const float* __restrict__ w,
                               const float* __restrict__ b,
                               float* __restrict__ out,
                               int Cin, int Cout, int HW) {
    __shared__ float s_w[8 * 128];
    int n = blockIdx.z;
    int coB = blockIdx.y * 8;
    int tid = threadIdx.x;
    for (int idx = tid; idx < 8 * Cin; idx += blockDim.x) {
        int col = idx / Cin, ci = idx % Cin;
        s_w[idx] = w[(coB + col) * Cin + ci];
    }
    __syncthreads();
    int px = blockIdx.x * blockDim.x + tid;
    if (px >= HW) return;
    const float* ip = in + (size_t)n * Cin * HW + px;
    float a[8];
#pragma unroll
    for (int c = 0; c < 8; c++) a[c] = 0.f;
    for (int ci = 0; ci < Cin; ci++) {
        float v = ip[(size_t)ci * HW];
#pragma unroll
        for (int c = 0; c < 8; c++) a[c] += v * s_w[c * Cin + ci];
    }
#pragma unroll
    for (int c = 0; c < 8; c++)
        out[((size_t)n * Cout + coB + c) * HW + px] = a[c] + b[coB + c];
}

// ---------------------------------------------------------------------------
// 2x2 average pool
// ---------------------------------------------------------------------------
__global__ void avgpool2_kernel(const float* __restrict__ in, float* __restrict__ out,
                                long total, int Ho, int Wo) {
    long i = (long)blockIdx.x * blockDim.x + threadIdx.x;
    if (i >= total) return;
    int wo = i % Wo;
    long t = i / Wo;
    int ho = t % Ho;
    long nc = t / Ho;
    int Hi = Ho * 2, Wi = Wo * 2;
    const float* p = in + nc * Hi * Wi + (2 * ho) * Wi + 2 * wo;
    out[i] = 0.25f * (p[0] + p[1] + p[Wi] + p[Wi + 1]);
}

// ---------------------------------------------------------------------------
// Global mean over H*W per (n,c): grid (C, N)
// ---------------------------------------------------------------------------
__global__ void gmean_kernel(const float* __restrict__ in, float* __restrict__ out,
                             int HW) {
    int C = gridDim.x;
    int c = blockIdx.x, n = blockIdx.y;
    const float* p = in + (size_t)(n * C + c) * HW;
    float s = 0.f;
    for (int i = threadIdx.x; i < HW; i += blockDim.x) s += p[i];
    float ts = blockReduceSum(s);
    if (threadIdx.x == 0) out[n * C + c] = ts / HW;
}

// ---------------------------------------------------------------------------
// Head: out[n,k] = dot(gm[n,:], w[k,:]) + b[k]. grid (10, N)
// ---------------------------------------------------------------------------
__global__ void head_kernel(const float* __restrict__ gm, const float* __restrict__ w,
                            const float* __restrict__ b, float* __restrict__ out, int C) {
    int k = blockIdx.x, n = blockIdx.y;
    float s = 0.f;
    for (int c = threadIdx.x; c < C; c += blockDim.x)
        s += gm[n * C + c] * w[k * C + c];
    float ts = blockReduceSum(s);
    if (threadIdx.x == 0) out[n * gridDim.x + k] = ts + b[k];
}

// ---------------------------------------------------------------------------
// Host-side helpers
// ---------------------------------------------------------------------------
static void conv3x3(const float* in, const float* w, const float* b, float* out,
                    int N, int Cin, int Cout, int H, int W, int flags) {
    if (W % 32 == 0 && H % 32 == 0) {
        int tilesX = W / 32, tilesY = H / 32;
        dim3 grid(tilesX * tilesY, Cout / 4, N), blk(16, 16);
        conv3x3_kernel<16, 16><<<grid, blk>>>(in, w, b, out, Cin, Cout, H, W, tilesX, flags);
    } else {
        int tilesX = (W + 23) / 24, tilesY = (H + 23) / 24;
        dim3 grid(tilesX * tilesY, Cout / 4, N), blk(12, 12);
        conv3x3_kernel<12, 12><<<grid, blk>>>(in, w, b, out, Cin, Cout, H, W, tilesX, flags);
    }
}

static void instnorm(float* x, const float* g, const float* b, int N, int C, int HW,
                     bool relu) {
    instnorm_kernel<<<dim3(C, N), 256>>>(x, g, b, HW, relu ? 1 : 0);
}

static void ode_block(float* y, const float* Wb, const float* bb,
                      int N, int C, int H, int W,
                      float* tin, float* k, float* z, float* acc) {
    const int nsteps = 4;
    const float dt = 1.0f / nsteps;
    long sz = (long)N * C * H * W;
    int gr = (int)((sz + 255) / 256);
    for (int i = 0; i < nsteps; i++) {
        int j = (i + 1 < nsteps) ? i + 1 : nsteps - 1;
        for (int s = 1; s <= 4; s++) {
            int bank = (s == 4) ? j : i;
            const float* Ws = Wb + (size_t)bank * C * C * 9;
            const float* bs = bb + (size_t)bank * C;
            const float* src = (s == 1) ? y : tin;
            conv3x3(src, Ws, bs, z, N, C, C, H, W, F_BIAS | F_RELU);
            instnorm(z, nullptr, nullptr, N, C, H * W, false);
            conv3x3(z, Ws, nullptr, k, N, C, C, H, W, F_NEG | F_TRANS);
            rk_update_kernel<<<gr, 256>>>(y, acc, tin, k, sz, s, dt);
        }
    }
}

extern "C" void kernel_launch(void* const* d_in, const int* in_sizes, int n_in,
                              void* d_out, int out_size) {
    const float* x       = (const float*)d_in[0];
    const float* stem_w  = (const float*)d_in[1];
    const float* stem_b  = (const float*)d_in[2];
    const float* norm1_g = (const float*)d_in[3];
    const float* norm1_b = (const float*)d_in[4];
    const float* ode1_W  = (const float*)d_in[5];
    const float* ode1_b  = (const float*)d_in[6];
    const float* conn1_w = (const float*)d_in[7];
    const float* conn1_b = (const float*)d_in[8];
    const float* norm3_g = (const float*)d_in[9];
    const float* norm3_b = (const float*)d_in[10];
    const float* ode2_W  = (const float*)d_in[11];
    const float* ode2_b  = (const float*)d_in[12];
    const float* conn2_w = (const float*)d_in[13];
    const float* conn2_b = (const float*)d_in[14];
    const float* norm4_g = (const float*)d_in[15];
    const float* norm4_b = (const float*)d_in[16];
    const float* ode3_W  = (const float*)d_in[17];
    const float* ode3_b  = (const float*)d_in[18];
    const float* head_w  = (const float*)d_in[19];
    const float* head_b  = (const float*)d_in[20];
    float* out = (float*)d_out;

    float* pool = nullptr;
    cudaGetSymbolAddress((void**)&pool, g_pool);
    float* A   = pool;
    float* B   = pool + 1ull * SLOT_ELEMS;  // tin / conn temp
    float* K   = pool + 2ull * SLOT_ELEMS;  // k / gm
    float* Z   = pool + 3ull * SLOT_ELEMS;  // rhs intermediate
    float* ACC = pool + 4ull * SLOT_ELEMS;  // RK accumulator

    const int N = 8;

    // Stem: conv3x3 3->64 + bias, instnorm(affine) + relu
    conv3x3(x, stem_w, stem_b, A, N, 3, 64, 96, 96, F_BIAS);
    instnorm(A, norm1_g, norm1_b, N, 64, 96 * 96, true);

    // ODE block 1: C=64, 96x96
    ode_block(A, ode1_W, ode1_b, N, 64, 96, 96, B, K, Z, ACC);

    // conn1: 1x1 64->128 + bias, instnorm(affine)+relu, avgpool2
    {
        int HW = 96 * 96;
        conv1x1_kernel<<<dim3((HW + 255) / 256, 128 / 8, N), 256>>>(
            A, conn1_w, conn1_b, B, 64, 128, HW);
        instnorm(B, norm3_g, norm3_b, N, 128, HW, true);
        long total = (long)N * 128 * 48 * 48;
        avgpool2_kernel<<<(int)((total + 255) / 256), 256>>>(B, A, total, 48, 48);
    }

    // ODE block 2: C=128, 48x48
    ode_block(A, ode2_W, ode2_b, N, 128, 48, 48, B, K, Z, ACC);

    // conn2: 1x1 128->256 + bias, instnorm(affine)+relu, avgpool2
    {
        int HW = 48 * 48;
        conv1x1_kernel<<<dim3((HW + 255) / 256, 256 / 8, N), 256>>>(
            A, conn2_w, conn2_b, B, 128, 256, HW);
        instnorm(B, norm4_g, norm4_b, N, 256, HW, true);
        long total = (long)N * 256 * 24 * 24;
        avgpool2_kernel<<<(int)((total + 255) / 256), 256>>>(B, A, total, 24, 24);
    }

    // ODE block 3: C=256, 24x24
    ode_block(A, ode3_W, ode3_b, N, 256, 24, 24, B, K, Z, ACC);

    // Global mean + head
    gmean_kernel<<<dim3(256, N), 256>>>(A, K, 24 * 24);
    head_kernel<<<dim3(10, N), 256>>>(K, head_w, head_b, out, 256);
}

// round 4
// speedup vs baseline: 2.7370x; 2.7370x over previous
#include <cuda_runtime.h>
#include <cuda_bf16.h>
#include <cstdint>

// ===========================================================================
// Helpers
// ===========================================================================
__device__ __forceinline__ uint32_t smem_to_u32(const void* p) {
    uint32_t a;
    asm("{ .reg .u64 t; cvta.to.shared.u64 t, %1; cvt.u32.u64 %0, t; }" : "=r"(a) : "l"(p));
    return a;
}

__device__ __forceinline__ void ldmx4(uint32_t* r, uint32_t addr) {
    asm volatile("ldmatrix.sync.aligned.m8n8.x4.shared.b16 {%0,%1,%2,%3}, [%4];"
                 : "=r"(r[0]), "=r"(r[1]), "=r"(r[2]), "=r"(r[3]) : "r"(addr));
}
__device__ __forceinline__ void ldmx2(uint32_t* r, uint32_t addr) {
    asm volatile("ldmatrix.sync.aligned.m8n8.x2.shared.b16 {%0,%1}, [%2];"
                 : "=r"(r[0]), "=r"(r[1]) : "r"(addr));
}
__device__ __forceinline__ void mma16816(float* d, const uint32_t* a, const uint32_t* b) {
    asm volatile(
        "mma.sync.aligned.m16n8k16.row.col.f32.bf16.bf16.f32 "
        "{%0,%1,%2,%3}, {%4,%5,%6,%7}, {%8,%9}, {%0,%1,%2,%3};"
        : "+f"(d[0]), "+f"(d[1]), "+f"(d[2]), "+f"(d[3])
        : "r"(a[0]), "r"(a[1]), "r"(a[2]), "r"(a[3]), "r"(b[0]), "r"(b[1]));
}

#define CP_ASYNC16(saddr, gptr) \
    asm volatile("cp.async.cg.shared.global [%0], [%1], 16;" :: "r"(saddr), "l"(gptr))
#define CP_COMMIT() asm volatile("cp.async.commit_group;" ::: "memory")
#define CP_WAIT(N)  asm volatile("cp.async.wait_group %0;" :: "n"(N) : "memory")

// paired-row SW128 swizzled offset: logical (row, 16B-chunk kc in 0..3)
__device__ __forceinline__ uint32_t swz_off(int r, int kc) {
    int p = r >> 1;
    return (uint32_t)(p * 128 + ((((r & 1) << 2) | kc) ^ (p & 7)) * 16);
}

// ===========================================================================
// Static buffers
// ===========================================================================
#define SLOT_ELEMS 9437184ull
__device__ __align__(256) float g_pool[5ull * SLOT_ELEMS];
#define BCOL_ELEMS 42467328ull
__device__ __align__(256) __nv_bfloat16 g_bhi[BCOL_ELEMS];
__device__ __align__(256) __nv_bfloat16 g_blo[BCOL_ELEMS];
#define WMAT_ELEMS 4718592ull
__device__ __align__(256) __nv_bfloat16 g_whi[WMAT_ELEMS];
__device__ __align__(256) __nv_bfloat16 g_wlo[WMAT_ELEMS];

#define F_BIAS 1
#define F_RELU 2
#define F_NEG  4

// ===========================================================================
// Block reduction
// ===========================================================================
__device__ __forceinline__ float blockReduceSum(float v) {
    __shared__ float sb[32];
    __syncthreads();
    int lane = threadIdx.x & 31, w = threadIdx.x >> 5;
#pragma unroll
    for (int o = 16; o > 0; o >>= 1) v += __shfl_down_sync(0xffffffffu, v, o);
    if (lane == 0) sb[w] = v;
    __syncthreads();
    int nw = blockDim.x >> 5;
    v = (threadIdx.x < nw) ? sb[threadIdx.x] : 0.f;
    if (w == 0) {
#pragma unroll
        for (int o = 16; o > 0; o >>= 1) v += __shfl_down_sync(0xffffffffu, v, o);
    }
    return v;
}

// ===========================================================================
// Stem conv (Cin=3), NCHW in -> CNHW out
// ===========================================================================
__global__ void stem_conv_kernel(const float* __restrict__ in,
                                 const float* __restrict__ wt,
                                 const float* __restrict__ bias,
                                 float* __restrict__ out,
                                 int Cin, int Cout, int H, int W,
                                 int tilesX, int Nimg) {
    constexpr int BX = 16, SW = 34, SH = 34;
    __shared__ float s_in[SH * SW];
    __shared__ float s_w[36];
    const int n = blockIdx.z;
    const int coB = blockIdx.y * 4;
    const int tX = blockIdx.x % tilesX, tY = blockIdx.x / tilesX;
    const int wbase = tX * 32 - 1, hbase = tY * 32 - 1;
    const int tx = threadIdx.x, ty = threadIdx.y;
    const int tid = ty * BX + tx;

    float acc[4][4];
#pragma unroll
    for (int a = 0; a < 4; a++)
#pragma unroll
        for (int b = 0; b < 4; b++) acc[a][b] = 0.f;

    for (int ci = 0; ci < Cin; ci++) {
        const float* ip = in + ((size_t)(n * Cin + ci)) * H * W;
        for (int idx = tid; idx < SH * SW; idx += 256) {
            int r = idx / SW, c = idx % SW;
            int gh = hbase + r, gw = wbase + c;
            float v = 0.f;
            if (gh >= 0 && gh < H && gw >= 0 && gw < W) v = ip[gh * W + gw];
            s_in[idx] = v;
        }
        if (tid < 36) {
            int col = tid / 9, k = tid % 9;
            s_w[tid] = wt[((coB + col) * Cin + ci) * 9 + k];
        }
        __syncthreads();
        float rr[4][4];
#pragma unroll
        for (int r = 0; r < 4; r++)
#pragma unroll
            for (int c = 0; c < 4; c++)
                rr[r][c] = s_in[(2 * ty + r) * SW + 2 * tx + c];
#pragma unroll
        for (int co = 0; co < 4; co++)
#pragma unroll
            for (int kh = 0; kh < 3; kh++)
#pragma unroll
                for (int kw = 0; kw < 3; kw++) {
                    float wv = s_w[co * 9 + kh * 3 + kw];
                    acc[co][0] += rr[kh][kw] * wv;
                    acc[co][1] += rr[kh][kw + 1] * wv;
                    acc[co][2] += rr[kh + 1][kw] * wv;
                    acc[co][3] += rr[kh + 1][kw + 1] * wv;
                }
        __syncthreads();
    }
#pragma unroll
    for (int co = 0; co < 4; co++) {
        int co_g = coB + co;
        float bv = bias[co_g];
#pragma unroll
        for (int oy = 0; oy < 2; oy++)
#pragma unroll
            for (int ox = 0; ox < 2; ox++) {
                int h = hbase + 1 + 2 * ty + oy;
                int w = wbase + 1 + 2 * tx + ox;
                out[(((size_t)co_g * Nimg + n) * H + h) * W + w] = acc[co][oy * 2 + ox] + bv;
            }
    }
}

// ===========================================================================
// Instance norm (CNHW), float4. grid (C, N)
// ===========================================================================
__global__ void instnorm_kernel(float* __restrict__ x,
                                const float* __restrict__ gamma,
                                const float* __restrict__ beta,
                                int HW, int relu) {
    size_t plane = (size_t)blockIdx.x * gridDim.y + blockIdx.y;
    float4* p = (float4*)(x + plane * HW);
    int n4 = HW >> 2;
    float s = 0.f, s2 = 0.f;
    for (int i = threadIdx.x; i < n4; i += blockDim.x) {
        float4 v = p[i];
        s += v.x + v.y + v.z + v.w;
        s2 += v.x * v.x + v.y * v.y + v.z * v.z + v.w * v.w;
    }
    float ts = blockReduceSum(s);
    float ts2 = blockReduceSum(s2);
    __shared__ float res[2];
    if (threadIdx.x == 0) {
        float mu = ts / HW;
        float var = ts2 / HW - mu * mu;
        res[0] = mu;
        res[1] = rsqrtf(var + 1e-5f);
    }
    __syncthreads();
    float mu = res[0], inv = res[1];
    float sc = inv, sh = -mu * inv;
    if (gamma) {
        float g = gamma[blockIdx.x], b = beta[blockIdx.x];
        sc = inv * g;
        sh = b - mu * inv * g;
    }
    for (int i = threadIdx.x; i < n4; i += blockDim.x) {
        float4 v = p[i];
        v.x = v.x * sc + sh; v.y = v.y * sc + sh;
        v.z = v.z * sc + sh; v.w = v.w * sc + sh;
        if (relu) {
            v.x = fmaxf(v.x, 0.f); v.y = fmaxf(v.y, 0.f);
            v.z = fmaxf(v.z, 0.f); v.w = fmaxf(v.w, 0.f);
        }
        p[i] = v;
    }
}

// ===========================================================================
// RK4 combine, float4
// ===========================================================================
__global__ void rk_update_kernel(float4* __restrict__ y, float4* __restrict__ acc,
                                 float4* __restrict__ tin, const float4* __restrict__ k,
                                 long n4, int stage, float dt) {
    long i = (long)blockIdx.x * blockDim.x + threadIdx.x;
    if (i >= n4) return;
    float4 kv = k[i];
    if (stage == 1) {
        float4 yv = y[i];
        acc[i] = kv;
        tin[i] = make_float4(yv.x + 0.5f * dt * kv.x, yv.y + 0.5f * dt * kv.y,
                             yv.z + 0.5f * dt * kv.z, yv.w + 0.5f * dt * kv.w);
    } else if (stage == 2) {
        float4 yv = y[i], a = acc[i];
        acc[i] = make_float4(a.x + 2.f * kv.x, a.y + 2.f * kv.y, a.z + 2.f * kv.z, a.w + 2.f * kv.w);
        tin[i] = make_float4(yv.x + 0.5f * dt * kv.x, yv.y + 0.5f * dt * kv.y,
                             yv.z + 0.5f * dt * kv.z, yv.w + 0.5f * dt * kv.w);
    } else if (stage == 3) {
        float4 yv = y[i], a = acc[i];
        acc[i] = make_float4(a.x + 2.f * kv.x, a.y + 2.f * kv.y, a.z + 2.f * kv.z, a.w + 2.f * kv.w);
        tin[i] = make_float4(yv.x + dt * kv.x, yv.y + dt * kv.y,
                             yv.z + dt * kv.z, yv.w + dt * kv.w);
    } else {
        float4 yv = y[i], a = acc[i];
        float c = dt / 6.f;
        y[i] = make_float4(yv.x + c * (a.x + kv.x), yv.y + c * (a.y + kv.y),
                           yv.z + c * (a.z + kv.z), yv.w + c * (a.w + kv.w));
    }
}

// ===========================================================================
// 1x1 conv (CNHW)
// ===========================================================================
__global__ void conv1x1_kernel(const float* __restrict__ in,
                               const float* __restrict__ w,
                               const float* __restrict__ b,
                               float* __restrict__ out,
                               int Cin, long PX) {
    __shared__ float s_w[8 * 128];
    int coB = blockIdx.y * 8;
    int tid = threadIdx.x;
    for (int idx = tid; idx < 8 * Cin; idx += blockDim.x) {
        int col = idx / Cin, ci = idx % Cin;
        s_w[idx] = w[(coB + col) * Cin + ci];
    }
    __syncthreads();
    long px = (long)blockIdx.x * blockDim.x + tid;
    if (px >= PX) return;
    float a[8];
#pragma unroll
    for (int c = 0; c < 8; c++) a[c] = 0.f;
    for (int ci = 0; ci < Cin; ci++) {
        float v = in[(size_t)ci * PX + px];
#pragma unroll
        for (int c = 0; c < 8; c++) a[c] += v * s_w[c * Cin + ci];
    }
#pragma unroll
    for (int c = 0; c < 8; c++)
        out[(size_t)(coB + c) * PX + px] = a[c] + b[coB + c];
}

// ===========================================================================
// avgpool 2x2 (flat planes)
// ===========================================================================
__global__ void avgpool2_kernel(const float* __restrict__ in, float* __restrict__ out,
                                long total, int Ho, int Wo) {
    long i = (long)blockIdx.x * blockDim.x + threadIdx.x;
    if (i >= total) return;
    int wo = i % Wo;
    long t = i / Wo;
    int ho = t % Ho;
    long nc = t / Ho;
    int Wi = Wo * 2;
    const float* p = in + nc * (4ll * Ho * Wo) + (2 * ho) * Wi + 2 * wo;
    out[i] = 0.25f * (p[0] + p[1] + p[Wi] + p[Wi + 1]);
}

// ===========================================================================
// gmean + head
// ===========================================================================
__global__ void gmean_kernel(const float* __restrict__ in, float* __restrict__ out, int HW) {
    size_t plane = (size_t)blockIdx.x * gridDim.y + blockIdx.y;
    const float* p = in + plane * HW;
    float s = 0.f;
    for (int i = threadIdx.x; i < HW; i += blockDim.x) s += p[i];
    float ts = blockReduceSum(s);
    if (threadIdx.x == 0) out[blockIdx.y * gridDim.x + blockIdx.x] = ts / HW;
}

__global__ void head_kernel(const float* __restrict__ gm, const float* __restrict__ w,
                            const float* __restrict__ b, float* __restrict__ out, int C) {
    int k = blockIdx.x, n = blockIdx.y;
    float s = 0.f;
    for (int c = threadIdx.x; c < C; c += blockDim.x)
        s += gm[n * C + c] * w[k * C + c];
    float ts = blockReduceSum(s);
    if (threadIdx.x == 0) out[n * gridDim.x + k] = ts + b[k];
}

// ===========================================================================
// Weight prep: [bank][dir][C][K] bf16 hi/lo.  dir0: W[m][ci][kh][kw];
// dir1: W[ci][m][2-kh][2-kw]
// ===========================================================================
__global__ void wprep_kernel(const float* __restrict__ W,
                             __nv_bfloat16* __restrict__ whi,
                             __nv_bfloat16* __restrict__ wlo,
                             int C) {
    int K = C * 9;
    long total = 8L * C * K;
    long idx = (long)blockIdx.x * blockDim.x + threadIdx.x;
    if (idx >= total) return;
    int k = (int)(idx % K);
    long t = idx / K;
    int m = (int)(t % C);
    int bd = (int)(t / C);
    int b = bd >> 1, dir = bd & 1;
    int ci = k / 9, r = k % 9, kh = r / 3, kw = r % 3;
    float v;
    if (dir == 0)
        v = W[(((size_t)b * C + m) * C + ci) * 9 + kh * 3 + kw];
    else
        v = W[(((size_t)b * C + ci) * C + m) * 9 + (2 - kh) * 3 + (2 - kw)];
    __nv_bfloat16 hi = __float2bfloat16(v);
    float lo = v - __bfloat162float(hi);
    whi[idx] = hi;
    wlo[idx] = __float2bfloat16(lo);
}

// ===========================================================================
// im2col hi/lo split. act CNHW fp32 -> B [px][K] bf16.
// grid (PX/4, K/64), block 256
// ===========================================================================
__global__ void im2col_kernel(const float* __restrict__ act,
                              __nv_bfloat16* __restrict__ bhi,
                              __nv_bfloat16* __restrict__ blo,
                              int C, int H, int W, int Nimg) {
    int K = C * 9;
    int k = blockIdx.y * 64 + (threadIdx.x & 63);
    long px = (long)blockIdx.x * 4 + (threadIdx.x >> 6);
    int HW = H * W;
    int n = (int)(px / HW);
    int rem = (int)(px - (long)n * HW);
    int h = rem / W, w = rem - h * W;
    int ci = k / 9, r = k - ci * 9;
    int dh = r / 3 - 1, dw = r - (r / 3) * 3 - 1;
    int hh = h + dh, ww = w + dw;
    float v = 0.f;
    if (hh >= 0 && hh < H && ww >= 0 && ww < W)
        v = act[(size_t)ci * ((size_t)Nimg * HW) + (size_t)n * HW + hh * W + ww];
    __nv_bfloat16 hi = __float2bfloat16(v);
    float lo = v - __bfloat162float(hi);
    size_t o = (size_t)px * K + k;
    bhi[o] = hi;
    blo[o] = __float2bfloat16(lo);
}

// ===========================================================================
// HMMA GEMM: D[m][n] = sum_k A[m][k]*B[n][k], bf16 3-term split, fp32 acc.
// A = weights [M][K], B = im2col [PX][K]. BK=32. 256 threads, 8 warps.
// smem per stage: Ahi|Alo|Bhi|Blo, paired-row SW128 layout.
// ===========================================================================
template <int ROWS>
__device__ __forceinline__ void load_tile(const __nv_bfloat16* __restrict__ g, int K,
                                          uint32_t sdst, int tid) {
#pragma unroll
    for (int i = 0; i < ROWS * 4 / 256; i++) {
        int idx = tid + i * 256;
        int r = idx >> 2, kc = idx & 3;
        const void* gp = g + (size_t)r * K + kc * 8;
        CP_ASYNC16(sdst + swz_off(r, kc), gp);
    }
}

template <int BM, int BN, int WARPS_M, int WARPS_N>
__global__ __launch_bounds__(256) void hgemm_conv(
    const __nv_bfloat16* __restrict__ Ahi, const __nv_bfloat16* __restrict__ Alo,
    const __nv_bfloat16* __restrict__ Bhi, const __nv_bfloat16* __restrict__ Blo,
    const float* __restrict__ bias, float* __restrict__ out,
    int K, long PX, int flags) {
    constexpr int BK = 32;
    constexpr int WM = BM / WARPS_M, WN = BN / WARPS_N;
    constexpr int MI = WM / 16, NI = WN / 8;
    constexpr int TA = BM * BK * 2;
    constexpr int TB = BN * BK * 2;
    constexpr int STAGE = 2 * TA + 2 * TB;
    extern __shared__ char smem[];

    const int tid = threadIdx.x, wid = tid >> 5, lane = tid & 31;
    const int wm = wid / WARPS_N, wn = wid % WARPS_N;
    const int m0 = blockIdx.y * BM;
    const long px0 = (long)blockIdx.x * BN;
    const uint32_t sb = smem_to_u32(smem);

    float acc[MI][NI][4];
#pragma unroll
    for (int mi = 0; mi < MI; mi++)
#pragma unroll
        for (int ni = 0; ni < NI; ni++)
#pragma unroll
            for (int q = 0; q < 4; q++) acc[mi][ni][q] = 0.f;

    const __nv_bfloat16* gAh = Ahi + (size_t)m0 * K;
    const __nv_bfloat16* gAl = Alo + (size_t)m0 * K;
    const __nv_bfloat16* gBh = Bhi + (size_t)px0 * K;
    const __nv_bfloat16* gBl = Blo + (size_t)px0 * K;

    const int nk = K / BK;

    // prologue: stage 0
    {
        uint32_t st = sb;
        load_tile<BM>(gAh, K, st, tid);
        load_tile<BM>(gAl, K, st + TA, tid);
        load_tile<BN>(gBh, K, st + 2 * TA, tid);
        load_tile<BN>(gBl, K, st + 2 * TA + TB, tid);
        CP_COMMIT();
    }

    for (int c = 0; c < nk; c++) {
        const int buf = c & 1;
        if (c + 1 < nk) {
            uint32_t st = sb + (buf ^ 1) * STAGE;
            int k0 = (c + 1) * BK;
            load_tile<BM>(gAh + k0, K, st, tid);
            load_tile<BM>(gAl + k0, K, st + TA, tid);
            load_tile<BN>(gBh + k0, K, st + 2 * TA, tid);
            load_tile<BN>(gBl + k0, K, st + 2 * TA + TB, tid);
            CP_COMMIT();
            CP_WAIT(1);
        } else {
            CP_WAIT(0);
        }
        __syncthreads();

        const uint32_t aB = sb + buf * STAGE;
        const uint32_t alB = aB + TA;
        const uint32_t bB = aB + 2 * TA;
        const uint32_t blB = bB + TB;

#pragma unroll
        for (int ks = 0; ks < 2; ks++) {
            uint32_t ah[MI][4], al[MI][4];
#pragma unroll
            for (int mi = 0; mi < MI; mi++) {
                int r = wm * WM + mi * 16 + (lane & 15);
                int kc = ks * 2 + (lane >> 4);
                uint32_t off = swz_off(r, kc);
                ldmx4(ah[mi], aB + off);
                ldmx4(al[mi], alB + off);
            }
            uint32_t bh[NI][2], bl[NI][2];
#pragma unroll
            for (int ni = 0; ni < NI; ni++) {
                int r = wn * WN + ni * 8 + (lane & 7);
                int kc = ks * 2 + ((lane >> 3) & 1);
                uint32_t off = swz_off(r, kc);
                ldmx2(bh[ni], bB + off);
                ldmx2(bl[ni], blB + off);
            }
#pragma unroll
            for (int mi = 0; mi < MI; mi++)
#pragma unroll
                for (int ni = 0; ni < NI; ni++) {
                    mma16816(acc[mi][ni], ah[mi], bh[ni]);
                    mma16816(acc[mi][ni], al[mi], bh[ni]);
                    mma16816(acc[mi][ni], ah[mi], bl[ni]);
                }
        }
        __syncthreads();
    }

    // epilogue
#pragma unroll
    for (int mi = 0; mi < MI; mi++) {
        int row = m0 + wm * WM + mi * 16 + (lane >> 2);
        float b0 = 0.f, b1 = 0.f;
        if (flags & F_BIAS) { b0 = bias[row]; b1 = bias[row + 8]; }
#pragma unroll
        for (int ni = 0; ni < NI; ni++) {
            long col = px0 + wn * WN + ni * 8 + (lane & 3) * 2;
            float2 v0 = make_float2(acc[mi][ni][0] + b0, acc[mi][ni][1] + b0);
            float2 v1 = make_float2(acc[mi][ni][2] + b1, acc[mi][ni][3] + b1);
            if (flags & F_RELU) {
                v0.x = fmaxf(v0.x, 0.f); v0.y = fmaxf(v0.y, 0.f);
                v1.x = fmaxf(v1.x, 0.f); v1.y = fmaxf(v1.y, 0.f);
            }
            if (flags & F_NEG) { v0.x = -v0.x; v0.y = -v0.y; v1.x = -v1.x; v1.y = -v1.y; }
            *(float2*)(out + (size_t)row * PX + col) = v0;
            *(float2*)(out + (size_t)(row + 8) * PX + col) = v1;
        }
    }
}

// ===========================================================================
// Host side
// ===========================================================================
struct DevPtrs {
    float* pool;
    __nv_bfloat16 *bhi, *blo, *whi, *wlo;
};

static void run_gemm(const __nv_bfloat16* ahi, const __nv_bfloat16* alo,
                     const __nv_bfloat16* bhi, const __nv_bfloat16* blo,
                     const float* bias, float* out,
                     int K, long PX, int C, int flags) {
    if (C == 64) {
        hgemm_conv<64, 128, 2, 4><<<dim3((unsigned)(PX / 128), 1), 256, 2 * (192 * 128)>>>(
            ahi, alo, bhi, blo, bias, out, K, PX, flags);
    } else if (C == 128) {
        hgemm_conv<128, 128, 2, 4><<<dim3((unsigned)(PX / 128), 1), 256, 2 * (256 * 128)>>>(
            ahi, alo, bhi, blo, bias, out, K, PX, flags);
    } else {
        hgemm_conv<128, 64, 4, 2><<<dim3((unsigned)(PX / 64), 2), 256, 2 * (192 * 128)>>>(
            ahi, alo, bhi, blo, bias, out, K, PX, flags);
    }
}

static void ode_block(DevPtrs& P, float* y, const float* Wb, const float* bb,
                      int Nimg, int C, int H, int W,
                      float* tin, float* kbuf, float* z, float* acc) {
    const int nsteps = 4;
    const float dt = 1.0f / nsteps;
    int K = 9 * C;
    long wtot = 8L * C * K;
    wprep_kernel<<<(unsigned)((wtot + 255) / 256), 256>>>(Wb, P.whi, P.wlo, C);

    long PX = (long)Nimg * H * W;
    long sz = PX * C;
    int gr = (int)((sz / 4 + 255) / 256);
    dim3 i2c_grid((unsigned)(PX / 4), K / 64);

    for (int i = 0; i < nsteps; i++) {
        int j = (i + 1 < nsteps) ? i + 1 : nsteps - 1;
        for (int s = 1; s <= 4; s++) {
            int bank = (s == 4) ? j : i;
            const __nv_bfloat16* wf_hi = P.whi + (size_t)(bank * 2 + 0) * C * K;
            const __nv_bfloat16* wf_lo = P.wlo + (size_t)(bank * 2 + 0) * C * K;
            const __nv_bfloat16* wt_hi = P.whi + (size_t)(bank * 2 + 1) * C * K;
            const __nv_bfloat16* wt_lo = P.wlo + (size_t)(bank * 2 + 1) * C * K;
            const float* bs = bb + (size_t)bank * C;
            const float* src = (s == 1) ? y : tin;

            im2col_kernel<<<i2c_grid, 256>>>(src, P.bhi, P.blo, C, H, W, Nimg);
            run_gemm(wf_hi, wf_lo, P.bhi, P.blo, bs, z, K, PX, C, F_BIAS | F_RELU);
            instnorm_kernel<<<dim3(C, Nimg), 256>>>(z, nullptr, nullptr, H * W, 0);
            im2col_kernel<<<i2c_grid, 256>>>(z, P.bhi, P.blo, C, H, W, Nimg);
            run_gemm(wt_hi, wt_lo, P.bhi, P.blo, bs, kbuf, K, PX, C, F_NEG);
            rk_update_kernel<<<gr, 256>>>((float4*)y, (float4*)acc, (float4*)tin,
                                          (const float4*)kbuf, sz / 4, s, dt);
        }
    }
}

extern "C" void kernel_launch(void* const* d_in, const int* in_sizes, int n_in,
                              void* d_out, int out_size) {
    const float* x       = (const float*)d_in[0];
    const float* stem_w  = (const float*)d_in[1];
    const float* stem_b  = (const float*)d_in[2];
    const float* norm1_g = (const float*)d_in[3];
    const float* norm1_b = (const float*)d_in[4];
    const float* ode1_W  = (const float*)d_in[5];
    const float* ode1_b  = (const float*)d_in[6];
    const float* conn1_w = (const float*)d_in[7];
    const float* conn1_b = (const float*)d_in[8];
    const float* norm3_g = (const float*)d_in[9];
    const float* norm3_b = (const float*)d_in[10];
    const float* ode2_W  = (const float*)d_in[11];
    const float* ode2_b  = (const float*)d_in[12];
    const float* conn2_w = (const float*)d_in[13];
    const float* conn2_b = (const float*)d_in[14];
    const float* norm4_g = (const float*)d_in[15];
    const float* norm4_b = (const float*)d_in[16];
    const float* ode3_W  = (const float*)d_in[17];
    const float* ode3_b  = (const float*)d_in[18];
    const float* head_w  = (const float*)d_in[19];
    const float* head_b  = (const float*)d_in[20];
    float* out = (float*)d_out;

    cudaFuncSetAttribute(hgemm_conv<64, 128, 2, 4>,
                         cudaFuncAttributeMaxDynamicSharedMemorySize, 2 * (192 * 128));
    cudaFuncSetAttribute(hgemm_conv<128, 128, 2, 4>,
                         cudaFuncAttributeMaxDynamicSharedMemorySize, 2 * (256 * 128));
    cudaFuncSetAttribute(hgemm_conv<128, 64, 4, 2>,
                         cudaFuncAttributeMaxDynamicSharedMemorySize, 2 * (192 * 128));

    DevPtrs P;
    cudaGetSymbolAddress((void**)&P.pool, g_pool);
    cudaGetSymbolAddress((void**)&P.bhi, g_bhi);
    cudaGetSymbolAddress((void**)&P.blo, g_blo);
    cudaGetSymbolAddress((void**)&P.whi, g_whi);
    cudaGetSymbolAddress((void**)&P.wlo, g_wlo);

    float* A   = P.pool;
    float* B   = P.pool + 1ull * SLOT_ELEMS;
    float* KB  = P.pool + 2ull * SLOT_ELEMS;
    float* Z   = P.pool + 3ull * SLOT_ELEMS;
    float* ACC = P.pool + 4ull * SLOT_ELEMS;

    const int N = 8;

    // Stem: conv3x3 3->64 (NCHW -> CNHW), instnorm affine + relu
    stem_conv_kernel<<<dim3(9, 16, N), dim3(16, 16)>>>(x, stem_w, stem_b, A,
                                                       3, 64, 96, 96, 3, N);
    instnorm_kernel<<<dim3(64, N), 256>>>(A, norm1_g, norm1_b, 96 * 96, 1);

    // ODE block 1: C=64, 96x96
    ode_block(P, A, ode1_W, ode1_b, N, 64, 96, 96, B, KB, Z, ACC);

    // conn1
    {
        long PX = (long)N * 96 * 96;
        conv1x1_kernel<<<dim3((unsigned)((PX + 255) / 256), 128 / 8), 256>>>(
            A, conn1_w, conn1_b, B, 64, PX);
        instnorm_kernel<<<dim3(128, N), 256>>>(B, norm3_g, norm3_b, 96 * 96, 1);
        long total = (long)N * 128 * 48 * 48;
        avgpool2_kernel<<<(unsigned)((total + 255) / 256), 256>>>(B, A, total, 48, 48);
    }

    // ODE block 2: C=128, 48x48
    ode_block(P, A, ode2_W, ode2_b, N, 128, 48, 48, B, KB, Z, ACC);

    // conn2
    {
        long PX = (long)N * 48 * 48;
        conv1x1_kernel<<<dim3((unsigned)((PX + 255) / 256), 256 / 8), 256>>>(
            A, conn2_w, conn2_b, B, 128, PX);
        instnorm_kernel<<<dim3(256, N), 256>>>(B, norm4_g, norm4_b, 48 * 48, 1);
        long total = (long)N * 256 * 24 * 24;
        avgpool2_kernel<<<(unsigned)((total + 255) / 256), 256>>>(B, A, total, 24, 24);
    }

    // ODE block 3: C=256, 24x24
    ode_block(P, A, ode3_W, ode3_b, N, 256, 24, 24, B, KB, Z, ACC);

    // Global mean + head
    gmean_kernel<<<dim3(256, N), 256>>>(A, KB, 24 * 24);
    head_kernel<<<dim3(10, N), 256>>>(KB, head_w, head_b, out, 256);
}

// round 5
// speedup vs baseline: 6.7938x; 2.4822x over previous
#include <cuda_runtime.h>
#include <cuda_bf16.h>
#include <cstdint>

// ===========================================================================
// Helpers
// ===========================================================================
__device__ __forceinline__ uint32_t smem_to_u32(const void* p) {
    uint32_t a;
    asm("{ .reg .u64 t; cvta.to.shared.u64 t, %1; cvt.u32.u64 %0, t; }" : "=r"(a) : "l"(p));
    return a;
}

__device__ __forceinline__ void ldmx4(uint32_t* r, uint32_t addr) {
    asm volatile("ldmatrix.sync.aligned.m8n8.x4.shared.b16 {%0,%1,%2,%3}, [%4];"
                 : "=r"(r[0]), "=r"(r[1]), "=r"(r[2]), "=r"(r[3]) : "r"(addr));
}
__device__ __forceinline__ void ldmx2(uint32_t* r, uint32_t addr) {
    asm volatile("ldmatrix.sync.aligned.m8n8.x2.shared.b16 {%0,%1}, [%2];"
                 : "=r"(r[0]), "=r"(r[1]) : "r"(addr));
}
__device__ __forceinline__ void mma16816(float* d, const uint32_t* a, const uint32_t* b) {
    asm volatile(
        "mma.sync.aligned.m16n8k16.row.col.f32.bf16.bf16.f32 "
        "{%0,%1,%2,%3}, {%4,%5,%6,%7}, {%8,%9}, {%0,%1,%2,%3};"
        : "+f"(d[0]), "+f"(d[1]), "+f"(d[2]), "+f"(d[3])
        : "r"(a[0]), "r"(a[1]), "r"(a[2]), "r"(a[3]), "r"(b[0]), "r"(b[1]));
}

#define CP_ASYNC16(saddr, gptr) \
    asm volatile("cp.async.cg.shared.global [%0], [%1], 16;" :: "r"(saddr), "l"(gptr))
#define CP_ASYNC16Z(saddr, gptr, sz) \
    asm volatile("cp.async.cg.shared.global [%0], [%1], 16, %2;" :: "r"(saddr), "l"(gptr), "r"(sz))
#define CP_COMMIT() asm volatile("cp.async.commit_group;" ::: "memory")
#define CP_WAIT(N)  asm volatile("cp.async.wait_group %0;" :: "n"(N) : "memory")

// paired-row SW128 swizzled offset: logical (row, 16B-chunk kc in 0..3)
__device__ __forceinline__ uint32_t swz_off(int r, int kc) {
    int p = r >> 1;
    return (uint32_t)(p * 128 + ((((r & 1) << 2) | kc) ^ (p & 7)) * 16);
}

__device__ __forceinline__ uint32_t pack_bf(__nv_bfloat16 a, __nv_bfloat16 b) {
    return (uint32_t)__bfloat16_as_ushort(a) | ((uint32_t)__bfloat16_as_ushort(b) << 16);
}

// split float4 -> hi/lo bf16 (as uint2 each)
__device__ __forceinline__ void split4(float4 v, uint2& hv, uint2& lv) {
    __nv_bfloat16 h0 = __float2bfloat16(v.x), h1 = __float2bfloat16(v.y);
    __nv_bfloat16 h2 = __float2bfloat16(v.z), h3 = __float2bfloat16(v.w);
    float l0 = v.x - __bfloat162float(h0), l1 = v.y - __bfloat162float(h1);
    float l2 = v.z - __bfloat162float(h2), l3 = v.w - __bfloat162float(h3);
    hv = make_uint2(pack_bf(h0, h1), pack_bf(h2, h3));
    lv = make_uint2(pack_bf(__float2bfloat16(l0), __float2bfloat16(l1)),
                    pack_bf(__float2bfloat16(l2), __float2bfloat16(l3)));
}

// ===========================================================================
// Static buffers
// ===========================================================================
#define SLOT_ELEMS 9437184ull
__device__ __align__(256) float g_pool[5ull * SLOT_ELEMS];
#define BCOL_ELEMS 42467328ull
__device__ __align__(256) __nv_bfloat16 g_bhi[BCOL_ELEMS];
__device__ __align__(256) __nv_bfloat16 g_blo[BCOL_ELEMS];
#define WMAT_ELEMS 4718592ull
__device__ __align__(256) __nv_bfloat16 g_whi[WMAT_ELEMS];
__device__ __align__(256) __nv_bfloat16 g_wlo[WMAT_ELEMS];
__device__ __align__(256) float g_partial[8 * 8 * 256 * 2];
__device__ __align__(256) float g_stats[8 * 256 * 2];
__device__ __align__(256) float g_gm[8 * 256];

#define F_BIAS 1
#define F_RELU 2
#define F_NEG  4

// ===========================================================================
// Block reduction (head)
// ===========================================================================
__device__ __forceinline__ float blockReduceSum(float v) {
    __shared__ float sb[32];
    __syncthreads();
    int lane = threadIdx.x & 31, w = threadIdx.x >> 5;
#pragma unroll
    for (int o = 16; o > 0; o >>= 1) v += __shfl_down_sync(0xffffffffu, v, o);
    if (lane == 0) sb[w] = v;
    __syncthreads();
    int nw = blockDim.x >> 5;
    v = (threadIdx.x < nw) ? sb[threadIdx.x] : 0.f;
    if (w == 0) {
#pragma unroll
        for (int o = 16; o > 0; o >>= 1) v += __shfl_down_sync(0xffffffffu, v, o);
    }
    return v;
}

// ===========================================================================
// Stem conv (Cin=3), NCHW in -> NPXC out
// ===========================================================================
__global__ void stem_conv_kernel(const float* __restrict__ in,
                                 const float* __restrict__ wt,
                                 const float* __restrict__ bias,
                                 float* __restrict__ out,
                                 int Cin, int Cout, int H, int W, int tilesX) {
    constexpr int BX = 16, SW = 34, SH = 34;
    __shared__ float s_in[SH * SW];
    __shared__ float s_w[36];
    const int n = blockIdx.z;
    const int coB = blockIdx.y * 4;
    const int tX = blockIdx.x % tilesX, tY = blockIdx.x / tilesX;
    const int wbase = tX * 32 - 1, hbase = tY * 32 - 1;
    const int tx = threadIdx.x, ty = threadIdx.y;
    const int tid = ty * BX + tx;

    float acc[4][4];
#pragma unroll
    for (int a = 0; a < 4; a++)
#pragma unroll
        for (int b = 0; b < 4; b++) acc[a][b] = 0.f;

    for (int ci = 0; ci < Cin; ci++) {
        const float* ip = in + ((size_t)(n * Cin + ci)) * H * W;
        for (int idx = tid; idx < SH * SW; idx += 256) {
            int r = idx / SW, c = idx % SW;
            int gh = hbase + r, gw = wbase + c;
            float v = 0.f;
            if (gh >= 0 && gh < H && gw >= 0 && gw < W) v = ip[gh * W + gw];
            s_in[idx] = v;
        }
        if (tid < 36) {
            int col = tid / 9, k = tid % 9;
            s_w[tid] = wt[((coB + col) * Cin + ci) * 9 + k];
        }
        __syncthreads();
        float rr[4][4];
#pragma unroll
        for (int r = 0; r < 4; r++)
#pragma unroll
            for (int c = 0; c < 4; c++)
                rr[r][c] = s_in[(2 * ty + r) * SW + 2 * tx + c];
#pragma unroll
        for (int co = 0; co < 4; co++)
#pragma unroll
            for (int kh = 0; kh < 3; kh++)
#pragma unroll
                for (int kw = 0; kw < 3; kw++) {
                    float wv = s_w[co * 9 + kh * 3 + kw];
                    acc[co][0] += rr[kh][kw] * wv;
                    acc[co][1] += rr[kh][kw + 1] * wv;
                    acc[co][2] += rr[kh + 1][kw] * wv;
                    acc[co][3] += rr[kh + 1][kw + 1] * wv;
                }
        __syncthreads();
    }
#pragma unroll
    for (int co = 0; co < 4; co++) {
        int co_g = coB + co;
        float bv = bias[co_g];
#pragma unroll
        for (int oy = 0; oy < 2; oy++)
#pragma unroll
            for (int ox = 0; ox < 2; ox++) {
                int h = hbase + 1 + 2 * ty + oy;
                int w = wbase + 1 + 2 * tx + ox;
                out[(((size_t)n * H + h) * W + w) * Cout + co_g] = acc[co][oy * 2 + ox] + bv;
            }
    }
}

// ===========================================================================
// Instance-norm stats pass 1: partial sums. grid (8, N), block 256.
// z layout NPXC; channel of a thread = tid % C (C | 256, base % 256 == 0).
// ===========================================================================
__global__ void stats_kernel(const float* __restrict__ z, float* __restrict__ partial,
                             int C, int HW, int N) {
    const int n = blockIdx.y, chunk = blockIdx.x;
    const long ipi = (long)HW * C;
    const long elems = ipi >> 3;  // 8 chunks
    const long base = (long)n * ipi + chunk * elems;
    const int tid = threadIdx.x;
    float s = 0.f, s2 = 0.f;
    for (long e = base + tid; e < base + elems; e += 256) {
        float v = z[e];
        s += v;
        s2 += v * v;
    }
    __shared__ float sb[256], sb2[256];
    sb[tid] = s;
    sb2[tid] = s2;
    __syncthreads();
    if (tid < C) {
        float a = sb[tid], b = sb2[tid];
        for (int j = tid + C; j < 256; j += C) { a += sb[j]; b += sb2[j]; }
        long o = (((long)chunk * N + n) * C + tid) * 2;
        partial[o] = a;
        partial[o + 1] = b;
    }
}

// pass 2: finalize per-(n,c) scale/shift. grid (N), block 256 (tid = c)
__global__ void reduce2_kernel(const float* __restrict__ partial,
                               const float* __restrict__ gamma,
                               const float* __restrict__ beta,
                               float* __restrict__ stats, int C, int N, int HW) {
    int n = blockIdx.x, c = threadIdx.x;
    if (c >= C) return;
    float s = 0.f, s2 = 0.f;
    for (int ch = 0; ch < 8; ch++) {
        long o = (((long)ch * N + n) * C + c) * 2;
        s += partial[o];
        s2 += partial[o + 1];
    }
    float mu = s / HW;
    float inv = rsqrtf(s2 / HW - mu * mu + 1e-5f);
    float g = gamma ? gamma[c] : 1.f;
    float b = beta ? beta[c] : 0.f;
    stats[(n * C + c) * 2] = inv * g;
    stats[(n * C + c) * 2 + 1] = b - mu * inv * g;
}

// apply: val = z*sc + sh (+relu); mode&1: write fp32, mode&2: write hi/lo split
__global__ void apply_kernel(const float* __restrict__ z, const float* __restrict__ stats,
                             float* __restrict__ outf,
                             __nv_bfloat16* __restrict__ ohi, __nv_bfloat16* __restrict__ olo,
                             int C, long ipi, int relu, int mode) {
    __shared__ float sst[512];
    const int n = blockIdx.y;
    for (int i = threadIdx.x; i < 2 * C; i += 256) sst[i] = stats[n * 2 * C + i];
    __syncthreads();
    const long n4 = ipi >> 2;
    const long v0 = (long)blockIdx.x * 256 + threadIdx.x;
    const int c0 = (int)((v0 << 2) & (C - 1));
    const float sc0 = sst[c0 * 2],       sh0 = sst[c0 * 2 + 1];
    const float sc1 = sst[(c0 + 1) * 2], sh1 = sst[(c0 + 1) * 2 + 1];
    const float sc2 = sst[(c0 + 2) * 2], sh2 = sst[(c0 + 2) * 2 + 1];
    const float sc3 = sst[(c0 + 3) * 2], sh3 = sst[(c0 + 3) * 2 + 1];
    const float4* zp = (const float4*)(z + (long)n * ipi);
    float4* op = outf ? (float4*)(outf + (long)n * ipi) : nullptr;
    uint2* hp = (uint2*)ohi + (long)n * (ipi >> 2);
    uint2* lp = (uint2*)olo + (long)n * (ipi >> 2);
    const long stride = (long)gridDim.x * 256;
    for (long v = v0; v < n4; v += stride) {
        float4 x = zp[v];
        x.x = x.x * sc0 + sh0; x.y = x.y * sc1 + sh1;
        x.z = x.z * sc2 + sh2; x.w = x.w * sc3 + sh3;
        if (relu) {
            x.x = fmaxf(x.x, 0.f); x.y = fmaxf(x.y, 0.f);
            x.z = fmaxf(x.z, 0.f); x.w = fmaxf(x.w, 0.f);
        }
        if (mode & 1) op[v] = x;
        if (mode & 2) {
            uint2 hv, lv;
            split4(x, hv, lv);
            hp[v] = hv;
            lp[v] = lv;
        }
    }
}

// plain split: y (fp32) -> hi/lo bf16
__global__ void split_kernel(const float4* __restrict__ y,
                             __nv_bfloat16* __restrict__ ohi, __nv_bfloat16* __restrict__ olo,
                             long n4) {
    long i = (long)blockIdx.x * blockDim.x + threadIdx.x;
    if (i >= n4) return;
    uint2 hv, lv;
    split4(y[i], hv, lv);
    ((uint2*)ohi)[i] = hv;
    ((uint2*)olo)[i] = lv;
}

// ===========================================================================
// RK4 combine + split of tin, float4
// ===========================================================================
__global__ void rk_update_kernel(float4* __restrict__ y, float4* __restrict__ acc,
                                 const float4* __restrict__ k,
                                 __nv_bfloat16* __restrict__ thi, __nv_bfloat16* __restrict__ tlo,
                                 long n4, int stage, float dt) {
    long i = (long)blockIdx.x * blockDim.x + threadIdx.x;
    if (i >= n4) return;
    float4 kv = k[i];
    float4 t;
    if (stage == 1) {
        float4 yv = y[i];
        acc[i] = kv;
        t = make_float4(yv.x + 0.5f * dt * kv.x, yv.y + 0.5f * dt * kv.y,
                        yv.z + 0.5f * dt * kv.z, yv.w + 0.5f * dt * kv.w);
    } else if (stage == 2) {
        float4 yv = y[i], a = acc[i];
        acc[i] = make_float4(a.x + 2.f * kv.x, a.y + 2.f * kv.y, a.z + 2.f * kv.z, a.w + 2.f * kv.w);
        t = make_float4(yv.x + 0.5f * dt * kv.x, yv.y + 0.5f * dt * kv.y,
                        yv.z + 0.5f * dt * kv.z, yv.w + 0.5f * dt * kv.w);
    } else if (stage == 3) {
        float4 yv = y[i], a = acc[i];
        acc[i] = make_float4(a.x + 2.f * kv.x, a.y + 2.f * kv.y, a.z + 2.f * kv.z, a.w + 2.f * kv.w);
        t = make_float4(yv.x + dt * kv.x, yv.y + dt * kv.y,
                        yv.z + dt * kv.z, yv.w + dt * kv.w);
    } else {
        float4 yv = y[i], a = acc[i];
        float c = dt / 6.f;
        t = make_float4(yv.x + c * (a.x + kv.x), yv.y + c * (a.y + kv.y),
                        yv.z + c * (a.z + kv.z), yv.w + c * (a.w + kv.w));
        y[i] = t;
    }
    uint2 hv, lv;
    split4(t, hv, lv);
    ((uint2*)thi)[i] = hv;
    ((uint2*)tlo)[i] = lv;
}

// ===========================================================================
// 1x1 conv, NPXC. grid (PX/64, Cout/64), block 256.
// smem: in_tile[64][CIN] + w_tile transposed [CIN][65]
// ===========================================================================
template <int CIN>
__global__ __launch_bounds__(256) void conv1x1_kernel(const float* __restrict__ in,
                                                      const float* __restrict__ w,
                                                      const float* __restrict__ bias,
                                                      float* __restrict__ out, int Cout) {
    extern __shared__ float cs[];
    float* s_in = cs;                 // 64 * CIN
    float* s_w = cs + 64 * CIN;       // [CIN][65]
    const int tid = threadIdx.x;
    const long px0 = (long)blockIdx.x * 64;
    const int co0 = blockIdx.y * 64;

    const float4* gin = (const float4*)(in + px0 * CIN);
    float4* s4 = (float4*)s_in;
    for (int idx = tid; idx < 64 * CIN / 4; idx += 256) s4[idx] = gin[idx];
    for (int idx = tid; idx < 64 * CIN; idx += 256) {
        int co = idx / CIN, ci = idx % CIN;
        s_w[ci * 65 + co] = w[(size_t)(co0 + co) * CIN + ci];
    }
    __syncthreads();

    const int pq = tid >> 4, cq = tid & 15;
    float a[4][4];
#pragma unroll
    for (int t = 0; t < 4; t++)
#pragma unroll
        for (int j = 0; j < 4; j++) a[t][j] = bias[co0 + cq * 4 + j];

    for (int ci = 0; ci < CIN; ci++) {
        float xi[4], wj[4];
#pragma unroll
        for (int t = 0; t < 4; t++) xi[t] = s_in[(pq * 4 + t) * CIN + ci];
#pragma unroll
        for (int j = 0; j < 4; j++) wj[j] = s_w[ci * 65 + cq * 4 + j];
#pragma unroll
        for (int t = 0; t < 4; t++)
#pragma unroll
            for (int j = 0; j < 4; j++) a[t][j] += xi[t] * wj[j];
    }
#pragma unroll
    for (int t = 0; t < 4; t++) {
        float4 v = make_float4(a[t][0], a[t][1], a[t][2], a[t][3]);
        *(float4*)(out + (px0 + pq * 4 + t) * Cout + co0 + cq * 4) = v;
    }
}

// ===========================================================================
// avgpool 2x2, NPXC
// ===========================================================================
__global__ void avgpool2_kernel(const float* __restrict__ in, float* __restrict__ out,
                                long total4, int Ho, int Wo, int C) {
    long i = (long)blockIdx.x * blockDim.x + threadIdx.x;
    if (i >= total4) return;
    const int C4 = C >> 2;
    long t = i / C4;
    int c4 = (int)(i - t * C4);
    int wo = (int)(t % Wo);
    long t2 = t / Wo;
    int ho = (int)(t2 % Ho);
    int n = (int)(t2 / Ho);
    const int Wi = 2 * Wo, Hi = 2 * Ho;
    const float4* p = (const float4*)in;
    long b = ((((long)n * Hi + 2 * ho) * Wi + 2 * wo)) * C4 + c4;
    float4 a0 = p[b], a1 = p[b + C4], a2 = p[b + (long)Wi * C4], a3 = p[b + (long)Wi * C4 + C4];
    float4 r = make_float4(0.25f * (a0.x + a1.x + a2.x + a3.x),
                           0.25f * (a0.y + a1.y + a2.y + a3.y),
                           0.25f * (a0.z + a1.z + a2.z + a3.z),
                           0.25f * (a0.w + a1.w + a2.w + a3.w));
    ((float4*)out)[i] = r;
}

// ===========================================================================
// gmean (NPXC, C==blockDim) + head
// ===========================================================================
__global__ void gmean_kernel(const float* __restrict__ y, float* __restrict__ gm,
                             int HW, int C) {
    int n = blockIdx.x, c = threadIdx.x;
    const float* p = y + (long)n * HW * C + c;
    float s = 0.f;
    for (int px = 0; px < HW; px++) s += p[(long)px * C];
    gm[n * C + c] = s / HW;
}

__global__ void head_kernel(const float* __restrict__ gm, const float* __restrict__ w,
                            const float* __restrict__ b, float* __restrict__ out, int C) {
    int k = blockIdx.x, n = blockIdx.y;
    float s = 0.f;
    for (int c = threadIdx.x; c < C; c += blockDim.x)
        s += gm[n * C + c] * w[k * C + c];
    float ts = blockReduceSum(s);
    if (threadIdx.x == 0) out[n * gridDim.x + k] = ts + b[k];
}

// ===========================================================================
// Weight prep: [bank][dir][C][K] bf16 hi/lo, K ordered k = r*C + ci.
// dir0: W[m][ci][r];  dir1: W[ci][m][8-r]
// ===========================================================================
__global__ void wprep_kernel(const float* __restrict__ W,
                             __nv_bfloat16* __restrict__ whi,
                             __nv_bfloat16* __restrict__ wlo,
                             int C) {
    int K = C * 9;
    long total = 8L * C * K;
    long idx = (long)blockIdx.x * blockDim.x + threadIdx.x;
    if (idx >= total) return;
    int k = (int)(idx % K);
    long t = idx / K;
    int m = (int)(t % C);
    int bd = (int)(t / C);
    int b = bd >> 1, dir = bd & 1;
    int ci = k % C, r = k / C;
    float v;
    if (dir == 0)
        v = W[(((size_t)b * C + m) * C + ci) * 9 + r];
    else
        v = W[(((size_t)b * C + ci) * C + m) * 9 + (8 - r)];
    __nv_bfloat16 hi = __float2bfloat16(v);
    float lo = v - __bfloat162float(hi);
    whi[idx] = hi;
    wlo[idx] = __float2bfloat16(lo);
}

// ===========================================================================
// Implicit-im2col HMMA GEMM.
// D[m][px] = sum_k A[m][k] * B[px][k], k = r*C + ci, B read on the fly from
// NPXC activation (hi/lo bf16). Output written NPXC via smem transpose.
// ===========================================================================
template <int BM>
__device__ __forceinline__ void load_w_tile(const __nv_bfloat16* __restrict__ g, int K,
                                            uint32_t sdst, int k0, int tid) {
#pragma unroll
    for (int i = 0; i < BM * 4 / 256; i++) {
        int idx = tid + i * 256;
        int r = idx >> 2, kc = idx & 3;
        CP_ASYNC16(sdst + swz_off(r, kc), g + (size_t)r * K + k0 + kc * 8);
    }
}

template <int BI>
__device__ __forceinline__ void load_act_tile(const __nv_bfloat16* __restrict__ X,
                                              uint32_t sdst,
                                              const long* pxT, const int* hT, const int* wT,
                                              int chunk, int lcpr, int C, int H, int W,
                                              int tid) {
    const int r9 = chunk >> lcpr;
    const int ci0 = (chunk & ((1 << lcpr) - 1)) << 5;
    const int dh = r9 / 3 - 1;
    const int dw = r9 - (r9 / 3) * 3 - 1;
#pragma unroll
    for (int i = 0; i < BI; i++) {
        int idx = tid + i * 256;
        int row = idx >> 2, kc = idx & 3;
        bool ok = ((unsigned)(hT[i] + dh) < (unsigned)H) &&
                  ((unsigned)(wT[i] + dw) < (unsigned)W);
        const __nv_bfloat16* p = X + (pxT[i] + (long)dh * W + dw) * C + ci0 + kc * 8;
        if (!ok) p = X;
        int sz = ok ? 16 : 0;
        CP_ASYNC16Z(sdst + swz_off(row, kc), p, sz);
    }
}

template <int BM, int BN, int WARPS_M, int WARPS_N>
__global__ __launch_bounds__(256) void hgemm_conv(
    const __nv_bfloat16* __restrict__ Ahi, const __nv_bfloat16* __restrict__ Alo,
    const __nv_bfloat16* __restrict__ Xhi, const __nv_bfloat16* __restrict__ Xlo,
    const float* __restrict__ bias, float* __restrict__ out,
    int C, int H, int W, int lcpr, int flags) {
    constexpr int BK = 32;
    constexpr int WM = BM / WARPS_M, WN = BN / WARPS_N;
    constexpr int MI = WM / 16, NI = WN / 8;
    constexpr int TA = BM * BK * 2;
    constexpr int TB = BN * BK * 2;
    constexpr int STAGE = 2 * TA + 2 * TB;
    constexpr int BI = BN * 4 / 256;
    constexpr int EST = BM + 4;
    extern __shared__ char smem[];

    const int tid = threadIdx.x, wid = tid >> 5, lane = tid & 31;
    const int wm = wid / WARPS_N, wn = wid % WARPS_N;
    const int m0 = blockIdx.y * BM;
    const long px0 = (long)blockIdx.x * BN;
    const uint32_t sb = smem_to_u32(smem);
    const int K = 9 * C;
    const int HW = H * W;

    // per-thread B-row coords
    long pxT[BI];
    int hT[BI], wT[BI];
#pragma unroll
    for (int i = 0; i < BI; i++) {
        int idx = tid + i * 256;
        long pxg = px0 + (idx >> 2);
        int n = (int)(pxg / HW);
        int rem = (int)(pxg - (long)n * HW);
        hT[i] = rem / W;
        wT[i] = rem - hT[i] * W;
        pxT[i] = pxg;
    }

    float acc[MI][NI][4];
#pragma unroll
    for (int mi = 0; mi < MI; mi++)
#pragma unroll
        for (int ni = 0; ni < NI; ni++)
#pragma unroll
            for (int q = 0; q < 4; q++) acc[mi][ni][q] = 0.f;

    const __nv_bfloat16* gAh = Ahi + (size_t)m0 * K;
    const __nv_bfloat16* gAl = Alo + (size_t)m0 * K;
    const int nk = K / BK;

    // prologue
    {
        uint32_t st = sb;
        load_w_tile<BM>(gAh, K, st, 0, tid);
        load_w_tile<BM>(gAl, K, st + TA, 0, tid);
        load_act_tile<BI>(Xhi, st + 2 * TA, pxT, hT, wT, 0, lcpr, C, H, W, tid);
        load_act_tile<BI>(Xlo, st + 2 * TA + TB, pxT, hT, wT, 0, lcpr, C, H, W, tid);
        CP_COMMIT();
    }

    for (int c = 0; c < nk; c++) {
        const int buf = c & 1;
        if (c + 1 < nk) {
            uint32_t st = sb + (buf ^ 1) * STAGE;
            int k0 = (c + 1) * BK;
            load_w_tile<BM>(gAh, K, st, k0, tid);
            load_w_tile<BM>(gAl, K, st + TA, k0, tid);
            load_act_tile<BI>(Xhi, st + 2 * TA, pxT, hT, wT, c + 1, lcpr, C, H, W, tid);
            load_act_tile<BI>(Xlo, st + 2 * TA + TB, pxT, hT, wT, c + 1, lcpr, C, H, W, tid);
            CP_COMMIT();
            CP_WAIT(1);
        } else {
            CP_WAIT(0);
        }
        __syncthreads();

        const uint32_t aB = sb + buf * STAGE;
        const uint32_t alB = aB + TA;
        const uint32_t bB = aB + 2 * TA;
        const uint32_t blB = bB + TB;

#pragma unroll
        for (int ks = 0; ks < 2; ks++) {
            uint32_t ah[MI][4], al[MI][4];
#pragma unroll
            for (int mi = 0; mi < MI; mi++) {
                int r = wm * WM + mi * 16 + (lane & 15);
                int kc = ks * 2 + (lane >> 4);
                uint32_t off = swz_off(r, kc);
                ldmx4(ah[mi], aB + off);
                ldmx4(al[mi], alB + off);
            }
            uint32_t bh[NI][2], bl[NI][2];
#pragma unroll
            for (int ni = 0; ni < NI; ni++) {
                int r = wn * WN + ni * 8 + (lane & 7);
                int kc = ks * 2 + ((lane >> 3) & 1);
                uint32_t off = swz_off(r, kc);
                ldmx2(bh[ni], bB + off);
                ldmx2(bl[ni], blB + off);
            }
#pragma unroll
            for (int mi = 0; mi < MI; mi++)
#pragma unroll
                for (int ni = 0; ni < NI; ni++) {
                    mma16816(acc[mi][ni], ah[mi], bh[ni]);
                    mma16816(acc[mi][ni], al[mi], bh[ni]);
                    mma16816(acc[mi][ni], ah[mi], bl[ni]);
                }
        }
        __syncthreads();
    }

    // epilogue: transpose via smem -> NPXC
    float* es = (float*)smem;
#pragma unroll
    for (int mi = 0; mi < MI; mi++) {
        int r0l = wm * WM + mi * 16 + (lane >> 2);
#pragma unroll
        for (int ni = 0; ni < NI; ni++) {
            int c0l = wn * WN + ni * 8 + (lane & 3) * 2;
            es[c0l * EST + r0l] = acc[mi][ni][0];
            es[(c0l + 1) * EST + r0l] = acc[mi][ni][1];
            es[c0l * EST + r0l + 8] = acc[mi][ni][2];
            es[(c0l + 1) * EST + r0l + 8] = acc[mi][ni][3];
        }
    }
    __syncthreads();
    for (int idx = tid; idx < BN * BM / 4; idx += 256) {
        int col = idx / (BM / 4);
        int ch4 = idx - col * (BM / 4);
        float4 v = *(float4*)&es[col * EST + ch4 * 4];
        int ch = m0 + ch4 * 4;
        if (flags & F_BIAS) {
            v.x += bias[ch]; v.y += bias[ch + 1];
            v.z += bias[ch + 2]; v.w += bias[ch + 3];
        }
        if (flags & F_RELU) {
            v.x = fmaxf(v.x, 0.f); v.y = fmaxf(v.y, 0.f);
            v.z = fmaxf(v.z, 0.f); v.w = fmaxf(v.w, 0.f);
        }
        if (flags & F_NEG) { v.x = -v.x; v.y = -v.y; v.z = -v.z; v.w = -v.w; }
        *(float4*)(out + (px0 + col) * C + ch) = v;
    }
}

// ===========================================================================
// Host side
// ===========================================================================
struct DevPtrs {
    float* pool;
    __nv_bfloat16 *thi, *tlo, *zhi, *zlo, *whi, *wlo;
    float *partial, *stats, *gm;
};

static void run_gemm(const __nv_bfloat16* ahi, const __nv_bfloat16* alo,
                     const __nv_bfloat16* xhi, const __nv_bfloat16* xlo,
                     const float* bias, float* out,
                     int C, int H, int W, int flags) {
    long PX = 8L * H * W;
    if (C == 64) {
        hgemm_conv<64, 128, 2, 4><<<dim3((unsigned)(PX / 128), 1), 256, 49152>>>(
            ahi, alo, xhi, xlo, bias, out, C, H, W, 1, flags);
    } else if (C == 128) {
        hgemm_conv<128, 128, 2, 4><<<dim3((unsigned)(PX / 128), 1), 256, 67584>>>(
            ahi, alo, xhi, xlo, bias, out, C, H, W, 2, flags);
    } else {
        hgemm_conv<128, 64, 4, 2><<<dim3((unsigned)(PX / 64), 2), 256, 49152>>>(
            ahi, alo, xhi, xlo, bias, out, C, H, W, 3, flags);
    }
}

static void ode_block(DevPtrs& P, float* y, const float* Wb, const float* bb,
                      int C, int H, int W, float* z, float* kbuf, float* acc) {
    const int Nimg = 8, nsteps = 4;
    const float dt = 1.0f / nsteps;
    const int K = 9 * C, HW = H * W;
    long wtot = 8L * C * K;
    wprep_kernel<<<(unsigned)((wtot + 255) / 256), 256>>>(Wb, P.whi, P.wlo, C);

    long PX = (long)Nimg * HW;
    long n4 = PX * C / 4;
    int gr = (int)((n4 + 255) / 256);
    long ipi = (long)HW * C;

    for (int i = 0; i < nsteps; i++) {
        int j = (i + 1 < nsteps) ? i + 1 : nsteps - 1;
        for (int s = 1; s <= 4; s++) {
            int bank = (s == 4) ? j : i;
            const __nv_bfloat16* wf_hi = P.whi + (size_t)(bank * 2 + 0) * C * K;
            const __nv_bfloat16* wf_lo = P.wlo + (size_t)(bank * 2 + 0) * C * K;
            const __nv_bfloat16* wt_hi = P.whi + (size_t)(bank * 2 + 1) * C * K;
            const __nv_bfloat16* wt_lo = P.wlo + (size_t)(bank * 2 + 1) * C * K;
            const float* bs = bb + (size_t)bank * C;

            run_gemm(wf_hi, wf_lo, P.thi, P.tlo, bs, z, C, H, W, F_BIAS | F_RELU);
            stats_kernel<<<dim3(8, Nimg), 256>>>(z, P.partial, C, HW, Nimg);
            reduce2_kernel<<<Nimg, 256>>>(P.partial, nullptr, nullptr, P.stats, C, Nimg, HW);
            apply_kernel<<<dim3(64, Nimg), 256>>>(z, P.stats, nullptr, P.zhi, P.zlo,
                                                  C, ipi, 0, 2);
            run_gemm(wt_hi, wt_lo, P.zhi, P.zlo, nullptr, kbuf, C, H, W, F_NEG);
            rk_update_kernel<<<gr, 256>>>((float4*)y, (float4*)acc, (const float4*)kbuf,
                                          P.thi, P.tlo, n4, s, dt);
        }
    }
}

extern "C" void kernel_launch(void* const* d_in, const int* in_sizes, int n_in,
                              void* d_out, int out_size) {
    const float* x       = (const float*)d_in[0];
    const float* stem_w  = (const float*)d_in[1];
    const float* stem_b  = (const float*)d_in[2];
    const float* norm1_g = (const float*)d_in[3];
    const float* norm1_b = (const float*)d_in[4];
    const float* ode1_W  = (const float*)d_in[5];
    const float* ode1_b  = (const float*)d_in[6];
    const float* conn1_w = (const float*)d_in[7];
    const float* conn1_b = (const float*)d_in[8];
    const float* norm3_g = (const float*)d_in[9];
    const float* norm3_b = (const float*)d_in[10];
    const float* ode2_W  = (const float*)d_in[11];
    const float* ode2_b  = (const float*)d_in[12];
    const float* conn2_w = (const float*)d_in[13];
    const float* conn2_b = (const float*)d_in[14];
    const float* norm4_g = (const float*)d_in[15];
    const float* norm4_b = (const float*)d_in[16];
    const float* ode3_W  = (const float*)d_in[17];
    const float* ode3_b  = (const float*)d_in[18];
    const float* head_w  = (const float*)d_in[19];
    const float* head_b  = (const float*)d_in[20];
    float* out = (float*)d_out;

    cudaFuncSetAttribute(hgemm_conv<64, 128, 2, 4>,
                         cudaFuncAttributeMaxDynamicSharedMemorySize, 49152);
    cudaFuncSetAttribute(hgemm_conv<128, 128, 2, 4>,
                         cudaFuncAttributeMaxDynamicSharedMemorySize, 67584);
    cudaFuncSetAttribute(hgemm_conv<128, 64, 4, 2>,
                         cudaFuncAttributeMaxDynamicSharedMemorySize, 49152);
    cudaFuncSetAttribute(conv1x1_kernel<128>,
                         cudaFuncAttributeMaxDynamicSharedMemorySize,
                         (64 * 128 + 65 * 128) * 4);

    DevPtrs P;
    cudaGetSymbolAddress((void**)&P.pool, g_pool);
    __nv_bfloat16* bhi;
    __nv_bfloat16* blo;
    cudaGetSymbolAddress((void**)&bhi, g_bhi);
    cudaGetSymbolAddress((void**)&blo, g_blo);
    P.thi = bhi;
    P.tlo = blo;
    P.zhi = bhi + 16777216ull;
    P.zlo = blo + 16777216ull;
    cudaGetSymbolAddress((void**)&P.whi, g_whi);
    cudaGetSymbolAddress((void**)&P.wlo, g_wlo);
    cudaGetSymbolAddress((void**)&P.partial, g_partial);
    cudaGetSymbolAddress((void**)&P.stats, g_stats);
    cudaGetSymbolAddress((void**)&P.gm, g_gm);

    float* A   = P.pool;                      // y
    float* B   = P.pool + 1ull * SLOT_ELEMS;  // conn temp
    float* KB  = P.pool + 2ull * SLOT_ELEMS;  // k / conv1x1 out
    float* Z   = P.pool + 3ull * SLOT_ELEMS;  // z
    float* ACC = P.pool + 4ull * SLOT_ELEMS;

    const int N = 8;

    // ---- Stem: conv3x3 3->64 (NCHW -> NPXC), instnorm(g,b)+relu, split
    stem_conv_kernel<<<dim3(9, 16, N), dim3(16, 16)>>>(x, stem_w, stem_b, Z, 3, 64, 96, 96, 3);
    stats_kernel<<<dim3(8, N), 256>>>(Z, P.partial, 64, 9216, N);
    reduce2_kernel<<<N, 256>>>(P.partial, norm1_g, norm1_b, P.stats, 64, N, 9216);
    apply_kernel<<<dim3(64, N), 256>>>(Z, P.stats, A, P.thi, P.tlo, 64, 9216L * 64, 1, 3);

    // ---- ODE block 1: C=64, 96x96
    ode_block(P, A, ode1_W, ode1_b, 64, 96, 96, Z, KB, ACC);

    // ---- conn1: 1x1 64->128, instnorm+relu, pool, split
    {
        long PX = (long)N * 9216;
        conv1x1_kernel<64><<<dim3((unsigned)(PX / 64), 2), 256, (64 * 64 + 65 * 64) * 4>>>(
            A, conn1_w, conn1_b, KB, 128);
        stats_kernel<<<dim3(8, N), 256>>>(KB, P.partial, 128, 9216, N);
        reduce2_kernel<<<N, 256>>>(P.partial, norm3_g, norm3_b, P.stats, 128, N, 9216);
        apply_kernel<<<dim3(64, N), 256>>>(KB, P.stats, Z, P.thi, P.tlo, 128, 9216L * 128, 1, 1);
        long total4 = (long)N * 48 * 48 * 128 / 4;
        avgpool2_kernel<<<(unsigned)((total4 + 255) / 256), 256>>>(Z, A, total4, 48, 48, 128);
        long n4 = (long)N * 48 * 48 * 128 / 4;
        split_kernel<<<(unsigned)((n4 + 255) / 256), 256>>>((float4*)A, P.thi, P.tlo, n4);
    }

    // ---- ODE block 2: C=128, 48x48
    ode_block(P, A, ode2_W, ode2_b, 128, 48, 48, Z, KB, ACC);

    // ---- conn2: 1x1 128->256, instnorm+relu, pool, split
    {
        long PX = (long)N * 2304;
        conv1x1_kernel<128><<<dim3((unsigned)(PX / 64), 4), 256, (64 * 128 + 65 * 128) * 4>>>(
            A, conn2_w, conn2_b, KB, 256);
        stats_kernel<<<dim3(8, N), 256>>>(KB, P.partial, 256, 2304, N);
        reduce2_kernel<<<N, 256>>>(P.partial, norm4_g, norm4_b, P.stats, 256, N, 2304);
        apply_kernel<<<dim3(64, N), 256>>>(KB, P.stats, Z, P.thi, P.tlo, 256, 2304L * 256, 1, 1);
        long total4 = (long)N * 24 * 24 * 256 / 4;
        avgpool2_kernel<<<(unsigned)((total4 + 255) / 256), 256>>>(Z, A, total4, 24, 24, 256);
        split_kernel<<<(unsigned)((total4 + 255) / 256), 256>>>((float4*)A, P.thi, P.tlo, total4);
    }

    // ---- ODE block 3: C=256, 24x24
    ode_block(P, A, ode3_W, ode3_b, 256, 24, 24, Z, KB, ACC);

    // ---- Global mean + head
    gmean_kernel<<<N, 256>>>(A, P.gm, 576, 256);
    head_kernel<<<dim3(10, N), 256>>>(P.gm, head_w, head_b, out, 256);
}

// round 7
// speedup vs baseline: 7.1197x; 1.0480x over previous
#include <cuda_runtime.h>
#include <cuda_bf16.h>
#include <cstdint>

// ===========================================================================
// Helpers
// ===========================================================================
__device__ __forceinline__ uint32_t smem_to_u32(const void* p) {
    uint32_t a;
    asm("{ .reg .u64 t; cvta.to.shared.u64 t, %1; cvt.u32.u64 %0, t; }" : "=r"(a) : "l"(p));
    return a;
}

__device__ __forceinline__ void ldmx4(uint32_t* r, uint32_t addr) {
    asm volatile("ldmatrix.sync.aligned.m8n8.x4.shared.b16 {%0,%1,%2,%3}, [%4];"
                 : "=r"(r[0]), "=r"(r[1]), "=r"(r[2]), "=r"(r[3]) : "r"(addr));
}
__device__ __forceinline__ void ldmx2(uint32_t* r, uint32_t addr) {
    asm volatile("ldmatrix.sync.aligned.m8n8.x2.shared.b16 {%0,%1}, [%2];"
                 : "=r"(r[0]), "=r"(r[1]) : "r"(addr));
}
__device__ __forceinline__ void mma16816(float* d, const uint32_t* a, const uint32_t* b) {
    asm volatile(
        "mma.sync.aligned.m16n8k16.row.col.f32.bf16.bf16.f32 "
        "{%0,%1,%2,%3}, {%4,%5,%6,%7}, {%8,%9}, {%0,%1,%2,%3};"
        : "+f"(d[0]), "+f"(d[1]), "+f"(d[2]), "+f"(d[3])
        : "r"(a[0]), "r"(a[1]), "r"(a[2]), "r"(a[3]), "r"(b[0]), "r"(b[1]));
}

#define CP_ASYNC16(saddr, gptr) \
    asm volatile("cp.async.cg.shared.global [%0], [%1], 16;" :: "r"(saddr), "l"(gptr))
#define CP_ASYNC16Z(saddr, gptr, sz) \
    asm volatile("cp.async.cg.shared.global [%0], [%1], 16, %2;" :: "r"(saddr), "l"(gptr), "r"(sz))
#define CP_COMMIT() asm volatile("cp.async.commit_group;" ::: "memory")
#define CP_WAIT(N)  asm volatile("cp.async.wait_group %0;" :: "n"(N) : "memory")

// paired-row SW128 swizzled offset: logical (row, 16B-chunk kc in 0..3)
__device__ __forceinline__ uint32_t swz_off(int r, int kc) {
    int p = r >> 1;
    return (uint32_t)(p * 128 + ((((r & 1) << 2) | kc) ^ (p & 7)) * 16);
}

__device__ __forceinline__ uint32_t pack_bf(__nv_bfloat16 a, __nv_bfloat16 b) {
    return (uint32_t)__bfloat16_as_ushort(a) | ((uint32_t)__bfloat16_as_ushort(b) << 16);
}

__device__ __forceinline__ void split4(float4 v, uint2& hv, uint2& lv) {
    __nv_bfloat16 h0 = __float2bfloat16(v.x), h1 = __float2bfloat16(v.y);
    __nv_bfloat16 h2 = __float2bfloat16(v.z), h3 = __float2bfloat16(v.w);
    float l0 = v.x - __bfloat162float(h0), l1 = v.y - __bfloat162float(h1);
    float l2 = v.z - __bfloat162float(h2), l3 = v.w - __bfloat162float(h3);
    hv = make_uint2(pack_bf(h0, h1), pack_bf(h2, h3));
    lv = make_uint2(pack_bf(__float2bfloat16(l0), __float2bfloat16(l1)),
                    pack_bf(__float2bfloat16(l2), __float2bfloat16(l3)));
}

// ===========================================================================
// Static buffers
// ===========================================================================
#define SLOT_ELEMS 9437184ull
__device__ __align__(256) float g_pool[5ull * SLOT_ELEMS];
#define BCOL_ELEMS 42467328ull
__device__ __align__(256) __nv_bfloat16 g_bhi[BCOL_ELEMS];
__device__ __align__(256) __nv_bfloat16 g_blo[BCOL_ELEMS];
#define WMAT_ELEMS 4718592ull
__device__ __align__(256) __nv_bfloat16 g_whi[WMAT_ELEMS];
__device__ __align__(256) __nv_bfloat16 g_wlo[WMAT_ELEMS];
// slot-indexed partials: up to 80 slots x 8 imgs x 256 ch x 2
__device__ __align__(256) float g_partial[80 * 8 * 256 * 2];
__device__ __align__(256) float g_stats[8 * 256 * 2];
__device__ __align__(256) float g_gm[8 * 256];

#define F_BIAS  1
#define F_RELU  2
#define F_NEG   4
#define F_STATS 8
#define F_RK    16

// ===========================================================================
// Block reduction (head)
// ===========================================================================
__device__ __forceinline__ float blockReduceSum(float v) {
    __shared__ float sb[32];
    __syncthreads();
    int lane = threadIdx.x & 31, w = threadIdx.x >> 5;
#pragma unroll
    for (int o = 16; o > 0; o >>= 1) v += __shfl_down_sync(0xffffffffu, v, o);
    if (lane == 0) sb[w] = v;
    __syncthreads();
    int nw = blockDim.x >> 5;
    v = (threadIdx.x < nw) ? sb[threadIdx.x] : 0.f;
    if (w == 0) {
#pragma unroll
        for (int o = 16; o > 0; o >>= 1) v += __shfl_down_sync(0xffffffffu, v, o);
    }
    return v;
}

// ===========================================================================
// Stem conv (Cin=3), NCHW in -> NPXC out
// ===========================================================================
__global__ void stem_conv_kernel(const float* __restrict__ in,
                                 const float* __restrict__ wt,
                                 const float* __restrict__ bias,
                                 float* __restrict__ out,
                                 int Cin, int Cout, int H, int W, int tilesX) {
    constexpr int BX = 16, SW = 34, SH = 34;
    __shared__ float s_in[SH * SW];
    __shared__ float s_w[36];
    const int n = blockIdx.z;
    const int coB = blockIdx.y * 4;
    const int tX = blockIdx.x % tilesX, tY = blockIdx.x / tilesX;
    const int wbase = tX * 32 - 1, hbase = tY * 32 - 1;
    const int tx = threadIdx.x, ty = threadIdx.y;
    const int tid = ty * BX + tx;

    float acc[4][4];
#pragma unroll
    for (int a = 0; a < 4; a++)
#pragma unroll
        for (int b = 0; b < 4; b++) acc[a][b] = 0.f;

    for (int ci = 0; ci < Cin; ci++) {
        const float* ip = in + ((size_t)(n * Cin + ci)) * H * W;
        for (int idx = tid; idx < SH * SW; idx += 256) {
            int r = idx / SW, c = idx % SW;
            int gh = hbase + r, gw = wbase + c;
            float v = 0.f;
            if (gh >= 0 && gh < H && gw >= 0 && gw < W) v = ip[gh * W + gw];
            s_in[idx] = v;
        }
        if (tid < 36) {
            int col = tid / 9, k = tid % 9;
            s_w[tid] = wt[((coB + col) * Cin + ci) * 9 + k];
        }
        __syncthreads();
        float rr[4][4];
#pragma unroll
        for (int r = 0; r < 4; r++)
#pragma unroll
            for (int c = 0; c < 4; c++)
                rr[r][c] = s_in[(2 * ty + r) * SW + 2 * tx + c];
#pragma unroll
        for (int co = 0; co < 4; co++)
#pragma unroll
            for (int kh = 0; kh < 3; kh++)
#pragma unroll
                for (int kw = 0; kw < 3; kw++) {
                    float wv = s_w[co * 9 + kh * 3 + kw];
                    acc[co][0] += rr[kh][kw] * wv;
                    acc[co][1] += rr[kh][kw + 1] * wv;
                    acc[co][2] += rr[kh + 1][kw] * wv;
                    acc[co][3] += rr[kh + 1][kw + 1] * wv;
                }
        __syncthreads();
    }
#pragma unroll
    for (int co = 0; co < 4; co++) {
        int co_g = coB + co;
        float bv = bias[co_g];
#pragma unroll
        for (int oy = 0; oy < 2; oy++)
#pragma unroll
            for (int ox = 0; ox < 2; ox++) {
                int h = hbase + 1 + 2 * ty + oy;
                int w = wbase + 1 + 2 * tx + ox;
                out[(((size_t)n * H + h) * W + w) * Cout + co_g] = acc[co][oy * 2 + ox] + bv;
            }
    }
}

// ===========================================================================
// Instance-norm stats (chunk layout) — used for stem/conn paths
// ===========================================================================
__global__ void stats_kernel(const float* __restrict__ z, float* __restrict__ partial,
                             int C, int HW, int N) {
    const int n = blockIdx.y, chunk = blockIdx.x;
    const long ipi = (long)HW * C;
    const long elems = ipi >> 3;
    const long base = (long)n * ipi + chunk * elems;
    const int tid = threadIdx.x;
    float s = 0.f, s2 = 0.f;
    for (long e = base + tid; e < base + elems; e += 256) {
        float v = z[e];
        s += v;
        s2 += v * v;
    }
    __shared__ float sb[256], sb2[256];
    sb[tid] = s;
    sb2[tid] = s2;
    __syncthreads();
    if (tid < C) {
        float a = sb[tid], b = sb2[tid];
        for (int j = tid + C; j < 256; j += C) { a += sb[j]; b += sb2[j]; }
        long o = (((long)chunk * N + n) * C + tid) * 2;
        partial[o] = a;
        partial[o + 1] = b;
    }
}

__global__ void reduce2_chunks(const float* __restrict__ partial,
                               const float* __restrict__ gamma,
                               const float* __restrict__ beta,
                               float* __restrict__ stats, int C, int N, int HW) {
    int n = blockIdx.x, c = threadIdx.x;
    if (c >= C) return;
    float s = 0.f, s2 = 0.f;
    for (int ch = 0; ch < 8; ch++) {
        long o = (((long)ch * N + n) * C + c) * 2;
        s += partial[o];
        s2 += partial[o + 1];
    }
    float mu = s / HW;
    float inv = rsqrtf(s2 / HW - mu * mu + 1e-5f);
    float g = gamma ? gamma[c] : 1.f;
    float b = beta ? beta[c] : 0.f;
    stats[(n * C + c) * 2] = inv * g;
    stats[(n * C + c) * 2 + 1] = b - mu * inv * g;
}

// slot-layout reduce for GEMM-epilogue stats (no affine)
__global__ void reduce2_direct(const float* __restrict__ partial,
                               float* __restrict__ stats, int C, int HW, int cpi, int N) {
    int n = blockIdx.x, c = threadIdx.x;
    if (c >= C) return;
    float s = 0.f, s2 = 0.f;
    for (int sl = 0; sl < cpi; sl++) {
        long o = (((long)sl * N + n) * C + c) * 2;
        s += partial[o];
        s2 += partial[o + 1];
    }
    float mu = s / HW;
    float inv = rsqrtf(s2 / HW - mu * mu + 1e-5f);
    stats[(n * C + c) * 2] = inv;
    stats[(n * C + c) * 2 + 1] = -mu * inv;
}

// apply: val = z*sc + sh (+relu); mode&1 write fp32, mode&2 write hi/lo
__global__ void apply_kernel(const float* __restrict__ z, const float* __restrict__ stats,
                             float* __restrict__ outf,
                             __nv_bfloat16* __restrict__ ohi, __nv_bfloat16* __restrict__ olo,
                             int C, long ipi, int relu, int mode) {
    __shared__ float sst[512];
    const int n = blockIdx.y;
    for (int i = threadIdx.x; i < 2 * C; i += 256) sst[i] = stats[n * 2 * C + i];
    __syncthreads();
    const long n4 = ipi >> 2;
    const long v0 = (long)blockIdx.x * 256 + threadIdx.x;
    const int c0 = (int)((v0 << 2) & (C - 1));
    const float sc0 = sst[c0 * 2],       sh0 = sst[c0 * 2 + 1];
    const float sc1 = sst[(c0 + 1) * 2], sh1 = sst[(c0 + 1) * 2 + 1];
    const float sc2 = sst[(c0 + 2) * 2], sh2 = sst[(c0 + 2) * 2 + 1];
    const float sc3 = sst[(c0 + 3) * 2], sh3 = sst[(c0 + 3) * 2 + 1];
    const float4* zp = (const float4*)(z + (long)n * ipi);
    float4* op = outf ? (float4*)(outf + (long)n * ipi) : nullptr;
    uint2* hp = (uint2*)ohi + (long)n * (ipi >> 2);
    uint2* lp = (uint2*)olo + (long)n * (ipi >> 2);
    const long stride = (long)gridDim.x * 256;
    for (long v = v0; v < n4; v += stride) {
        float4 x = zp[v];
        x.x = x.x * sc0 + sh0; x.y = x.y * sc1 + sh1;
        x.z = x.z * sc2 + sh2; x.w = x.w * sc3 + sh3;
        if (relu) {
            x.x = fmaxf(x.x, 0.f); x.y = fmaxf(x.y, 0.f);
            x.z = fmaxf(x.z, 0.f); x.w = fmaxf(x.w, 0.f);
        }
        if (mode & 1) op[v] = x;
        if (mode & 2) {
            uint2 hv, lv;
            split4(x, hv, lv);
            hp[v] = hv;
            lp[v] = lv;
        }
    }
}

// plain split: fp32 -> hi/lo bf16
__global__ void split_kernel(const float4* __restrict__ y,
                             __nv_bfloat16* __restrict__ ohi, __nv_bfloat16* __restrict__ olo,
                             long n4) {
    long i = (long)blockIdx.x * blockDim.x + threadIdx.x;
    if (i >= n4) return;
    uint2 hv, lv;
    split4(y[i], hv, lv);
    ((uint2*)ohi)[i] = hv;
    ((uint2*)olo)[i] = lv;
}

// ===========================================================================
// 1x1 conv, NPXC
// ===========================================================================
template <int CIN>
__global__ __launch_bounds__(256) void conv1x1_kernel(const float* __restrict__ in,
                                                      const float* __restrict__ w,
                                                      const float* __restrict__ bias,
                                                      float* __restrict__ out, int Cout) {
    extern __shared__ float cs[];
    float* s_in = cs;
    float* s_w = cs + 64 * CIN;
    const int tid = threadIdx.x;
    const long px0 = (long)blockIdx.x * 64;
    const int co0 = blockIdx.y * 64;

    const float4* gin = (const float4*)(in + px0 * CIN);
    float4* s4 = (float4*)s_in;
    for (int idx = tid; idx < 64 * CIN / 4; idx += 256) s4[idx] = gin[idx];
    for (int idx = tid; idx < 64 * CIN; idx += 256) {
        int co = idx / CIN, ci = idx % CIN;
        s_w[ci * 65 + co] = w[(size_t)(co0 + co) * CIN + ci];
    }
    __syncthreads();

    const int pq = tid >> 4, cq = tid & 15;
    float a[4][4];
#pragma unroll
    for (int t = 0; t < 4; t++)
#pragma unroll
        for (int j = 0; j < 4; j++) a[t][j] = bias[co0 + cq * 4 + j];

    for (int ci = 0; ci < CIN; ci++) {
        float xi[4], wj[4];
#pragma unroll
        for (int t = 0; t < 4; t++) xi[t] = s_in[(pq * 4 + t) * CIN + ci];
#pragma unroll
        for (int j = 0; j < 4; j++) wj[j] = s_w[ci * 65 + cq * 4 + j];
#pragma unroll
        for (int t = 0; t < 4; t++)
#pragma unroll
            for (int j = 0; j < 4; j++) a[t][j] += xi[t] * wj[j];
    }
#pragma unroll
    for (int t = 0; t < 4; t++) {
        float4 v = make_float4(a[t][0], a[t][1], a[t][2], a[t][3]);
        *(float4*)(out + (px0 + pq * 4 + t) * Cout + co0 + cq * 4) = v;
    }
}

// ===========================================================================
// avgpool 2x2, NPXC
// ===========================================================================
__global__ void avgpool2_kernel(const float* __restrict__ in, float* __restrict__ out,
                                long total4, int Ho, int Wo, int C) {
    long i = (long)blockIdx.x * blockDim.x + threadIdx.x;
    if (i >= total4) return;
    const int C4 = C >> 2;
    long t = i / C4;
    int c4 = (int)(i - t * C4);
    int wo = (int)(t % Wo);
    long t2 = t / Wo;
    int ho = (int)(t2 % Ho);
    int n = (int)(t2 / Ho);
    const int Wi = 2 * Wo, Hi = 2 * Ho;
    const float4* p = (const float4*)in;
    long b = ((((long)n * Hi + 2 * ho) * Wi + 2 * wo)) * C4 + c4;
    float4 a0 = p[b], a1 = p[b + C4], a2 = p[b + (long)Wi * C4], a3 = p[b + (long)Wi * C4 + C4];
    float4 r = make_float4(0.25f * (a0.x + a1.x + a2.x + a3.x),
                           0.25f * (a0.y + a1.y + a2.y + a3.y),
                           0.25f * (a0.z + a1.z + a2.z + a3.z),
                           0.25f * (a0.w + a1.w + a2.w + a3.w));
    ((float4*)out)[i] = r;
}

// ===========================================================================
// gmean + head
// ===========================================================================
__global__ void gmean_kernel(const float* __restrict__ y, float* __restrict__ gm,
                             int HW, int C) {
    int n = blockIdx.x, c = threadIdx.x;
    const float* p = y + (long)n * HW * C + c;
    float s = 0.f;
    for (int px = 0; px < HW; px++) s += p[(long)px * C];
    gm[n * C + c] = s / HW;
}

__global__ void head_kernel(const float* __restrict__ gm, const float* __restrict__ w,
                            const float* __restrict__ b, float* __restrict__ out, int C) {
    int k = blockIdx.x, n = blockIdx.y;
    float s = 0.f;
    for (int c = threadIdx.x; c < C; c += blockDim.x)
        s += gm[n * C + c] * w[k * C + c];
    float ts = blockReduceSum(s);
    if (threadIdx.x == 0) out[n * gridDim.x + k] = ts + b[k];
}

// ===========================================================================
// Weight prep: [bank][dir][C][K], k = r*C + ci. dir0 fwd, dir1 trans+flip
// ===========================================================================
__global__ void wprep_kernel(const float* __restrict__ W,
                             __nv_bfloat16* __restrict__ whi,
                             __nv_bfloat16* __restrict__ wlo,
                             int C) {
    int K = C * 9;
    long total = 8L * C * K;
    long idx = (long)blockIdx.x * blockDim.x + threadIdx.x;
    if (idx >= total) return;
    int k = (int)(idx % K);
    long t = idx / K;
    int m = (int)(t % C);
    int bd = (int)(t / C);
    int b = bd >> 1, dir = bd & 1;
    int ci = k % C, r = k / C;
    float v;
    if (dir == 0)
        v = W[(((size_t)b * C + m) * C + ci) * 9 + r];
    else
        v = W[(((size_t)b * C + ci) * C + m) * 9 + (8 - r)];
    __nv_bfloat16 hi = __float2bfloat16(v);
    float lo = v - __bfloat162float(hi);
    whi[idx] = hi;
    wlo[idx] = __float2bfloat16(lo);
}

// ===========================================================================
// Implicit-im2col HMMA GEMM with fused epilogues
// ===========================================================================
template <int BM>
__device__ __forceinline__ void load_w_tile(const __nv_bfloat16* __restrict__ g, int K,
                                            uint32_t sdst, int k0, int tid) {
#pragma unroll
    for (int i = 0; i < BM * 4 / 256; i++) {
        int idx = tid + i * 256;
        int r = idx >> 2, kc = idx & 3;
        CP_ASYNC16(sdst + swz_off(r, kc), g + (size_t)r * K + k0 + kc * 8);
    }
}

template <int BI>
__device__ __forceinline__ void load_act_tile(const __nv_bfloat16* __restrict__ X,
                                              uint32_t sdst,
                                              const long* pxT, const int* hT, const int* wT,
                                              int chunk, int lcpr, int C, int H, int W,
                                              int tid) {
    const int r9 = chunk >> lcpr;
    const int ci0 = (chunk & ((1 << lcpr) - 1)) << 5;
    const int dh = r9 / 3 - 1;
    const int dw = r9 - (r9 / 3) * 3 - 1;
#pragma unroll
    for (int i = 0; i < BI; i++) {
        int idx = tid + i * 256;
        int row = idx >> 2, kc = idx & 3;
        bool ok = ((unsigned)(hT[i] + dh) < (unsigned)H) &&
                  ((unsigned)(wT[i] + dw) < (unsigned)W);
        const __nv_bfloat16* p = X + (pxT[i] + (long)dh * W + dw) * C + ci0 + kc * 8;
        if (!ok) p = X;
        int sz = ok ? 16 : 0;
        CP_ASYNC16Z(sdst + swz_off(row, kc), p, sz);
    }
}

template <int BM, int BN, int WARPS_M, int WARPS_N>
__global__ __launch_bounds__(256) void hgemm_conv(
    const __nv_bfloat16* __restrict__ Ahi, const __nv_bfloat16* __restrict__ Alo,
    const __nv_bfloat16* __restrict__ Xhi, const __nv_bfloat16* __restrict__ Xlo,
    const float* __restrict__ bias, float* __restrict__ out,
    float* __restrict__ partial,
    float* __restrict__ yb, float* __restrict__ accb,
    __nv_bfloat16* __restrict__ thi, __nv_bfloat16* __restrict__ tlo,
    int C, int H, int W, int lcpr, int flags, int stage, float dt) {
    constexpr int BK = 32;
    constexpr int WM = BM / WARPS_M, WN = BN / WARPS_N;
    constexpr int MI = WM / 16, NI = WN / 8;
    constexpr int TA = BM * BK * 2;
    constexpr int TB = BN * BK * 2;
    constexpr int STAGE = 2 * TA + 2 * TB;
    constexpr int BI = BN * 4 / 256;
    constexpr int EST = BM + 4;
    extern __shared__ char smem[];

    const int tid = threadIdx.x, wid = tid >> 5, lane = tid & 31;
    const int wm = wid / WARPS_N, wn = wid % WARPS_N;
    const int m0 = blockIdx.y * BM;
    const long px0 = (long)blockIdx.x * BN;
    const uint32_t sb = smem_to_u32(smem);
    const int K = 9 * C;
    const int HW = H * W;

    long pxT[BI];
    int hT[BI], wT[BI];
#pragma unroll
    for (int i = 0; i < BI; i++) {
        int idx = tid + i * 256;
        long pxg = px0 + (idx >> 2);
        int n = (int)(pxg / HW);
        int rem = (int)(pxg - (long)n * HW);
        hT[i] = rem / W;
        wT[i] = rem - hT[i] * W;
        pxT[i] = pxg;
    }

    float acc[MI][NI][4];
#pragma unroll
    for (int mi = 0; mi < MI; mi++)
#pragma unroll
        for (int ni = 0; ni < NI; ni++)
#pragma unroll
            for (int q = 0; q < 4; q++) acc[mi][ni][q] = 0.f;

    const __nv_bfloat16* gAh = Ahi + (size_t)m0 * K;
    const __nv_bfloat16* gAl = Alo + (size_t)m0 * K;
    const int nk = K / BK;

    {
        uint32_t st = sb;
        load_w_tile<BM>(gAh, K, st, 0, tid);
        load_w_tile<BM>(gAl, K, st + TA, 0, tid);
        load_act_tile<BI>(Xhi, st + 2 * TA, pxT, hT, wT, 0, lcpr, C, H, W, tid);
        load_act_tile<BI>(Xlo, st + 2 * TA + TB, pxT, hT, wT, 0, lcpr, C, H, W, tid);
        CP_COMMIT();
    }

    for (int c = 0; c < nk; c++) {
        const int buf = c & 1;
        if (c + 1 < nk) {
            uint32_t st = sb + (buf ^ 1) * STAGE;
            int k0 = (c + 1) * BK;
            load_w_tile<BM>(gAh, K, st, k0, tid);
            load_w_tile<BM>(gAl, K, st + TA, k0, tid);
            load_act_tile<BI>(Xhi, st + 2 * TA, pxT, hT, wT, c + 1, lcpr, C, H, W, tid);
            load_act_tile<BI>(Xlo, st + 2 * TA + TB, pxT, hT, wT, c + 1, lcpr, C, H, W, tid);
            CP_COMMIT();
            CP_WAIT(1);
        } else {
            CP_WAIT(0);
        }
        __syncthreads();

        const uint32_t aB = sb + buf * STAGE;
        const uint32_t alB = aB + TA;
        const uint32_t bB = aB + 2 * TA;
        const uint32_t blB = bB + TB;

#pragma unroll
        for (int ks = 0; ks < 2; ks++) {
            uint32_t ah[MI][4], al[MI][4];
#pragma unroll
            for (int mi = 0; mi < MI; mi++) {
                int r = wm * WM + mi * 16 + (lane & 15);
                int kc = ks * 2 + (lane >> 4);
                uint32_t off = swz_off(r, kc);
                ldmx4(ah[mi], aB + off);
                ldmx4(al[mi], alB + off);
            }
            uint32_t bh[NI][2], bl[NI][2];
#pragma unroll
            for (int ni = 0; ni < NI; ni++) {
                int r = wn * WN + ni * 8 + (lane & 7);
                int kc = ks * 2 + ((lane >> 3) & 1);
                uint32_t off = swz_off(r, kc);
                ldmx2(bh[ni], bB + off);
                ldmx2(bl[ni], blB + off);
            }
#pragma unroll
            for (int mi = 0; mi < MI; mi++)
#pragma unroll
                for (int ni = 0; ni < NI; ni++) {
                    mma16816(acc[mi][ni], ah[mi], bh[ni]);
                    mma16816(acc[mi][ni], al[mi], bh[ni]);
                    mma16816(acc[mi][ni], ah[mi], bl[ni]);
                }
        }
        __syncthreads();
    }

    // ---- epilogue: transpose via smem ----
    float* es = (float*)smem;
#pragma unroll
    for (int mi = 0; mi < MI; mi++) {
        int r0l = wm * WM + mi * 16 + (lane >> 2);
#pragma unroll
        for (int ni = 0; ni < NI; ni++) {
            int c0l = wn * WN + ni * 8 + (lane & 3) * 2;
            es[c0l * EST + r0l] = acc[mi][ni][0];
            es[(c0l + 1) * EST + r0l] = acc[mi][ni][1];
            es[c0l * EST + r0l + 8] = acc[mi][ni][2];
            es[(c0l + 1) * EST + r0l + 8] = acc[mi][ni][3];
        }
    }
    __syncthreads();

    if (flags & F_RK) {
        // fused RK4 stage update; tile value IS k (after NEG)
        const float hdt = 0.5f * dt, sdt = dt / 6.f;
        for (int idx = tid; idx < BN * BM / 4; idx += 256) {
            int col = idx / (BM / 4);
            int ch4 = idx - col * (BM / 4);
            float4 kv = *(float4*)&es[col * EST + ch4 * 4];
            kv.x = -kv.x; kv.y = -kv.y; kv.z = -kv.z; kv.w = -kv.w;
            long i4 = ((px0 + col) * C + m0 + ch4 * 4) >> 2;
            float4 yv = ((const float4*)yb)[i4];
            float4 t;
            if (stage == 1) {
                ((float4*)accb)[i4] = kv;
                t = make_float4(yv.x + hdt * kv.x, yv.y + hdt * kv.y,
                                yv.z + hdt * kv.z, yv.w + hdt * kv.w);
            } else if (stage == 2) {
                float4 a = ((const float4*)accb)[i4];
                ((float4*)accb)[i4] = make_float4(a.x + 2.f * kv.x, a.y + 2.f * kv.y,
                                                  a.z + 2.f * kv.z, a.w + 2.f * kv.w);
                t = make_float4(yv.x + hdt * kv.x, yv.y + hdt * kv.y,
                                yv.z + hdt * kv.z, yv.w + hdt * kv.w);
            } else if (stage == 3) {
                float4 a = ((const float4*)accb)[i4];
                ((float4*)accb)[i4] = make_float4(a.x + 2.f * kv.x, a.y + 2.f * kv.y,
                                                  a.z + 2.f * kv.z, a.w + 2.f * kv.w);
                t = make_float4(yv.x + dt * kv.x, yv.y + dt * kv.y,
                                yv.z + dt * kv.z, yv.w + dt * kv.w);
            } else {
                float4 a = ((const float4*)accb)[i4];
                t = make_float4(yv.x + sdt * (a.x + kv.x), yv.y + sdt * (a.y + kv.y),
                                yv.z + sdt * (a.z + kv.z), yv.w + sdt * (a.w + kv.w));
                ((float4*)yb)[i4] = t;
            }
            uint2 hv, lv;
            split4(t, hv, lv);
            ((uint2*)thi)[i4] = hv;
            ((uint2*)tlo)[i4] = lv;
        }
    } else {
        for (int idx = tid; idx < BN * BM / 4; idx += 256) {
            int col = idx / (BM / 4);
            int ch4 = idx - col * (BM / 4);
            float4 v = *(float4*)&es[col * EST + ch4 * 4];
            int ch = m0 + ch4 * 4;
            if (flags & F_BIAS) {
                v.x += bias[ch]; v.y += bias[ch + 1];
                v.z += bias[ch + 2]; v.w += bias[ch + 3];
            }
            if (flags & F_RELU) {
                v.x = fmaxf(v.x, 0.f); v.y = fmaxf(v.y, 0.f);
                v.z = fmaxf(v.z, 0.f); v.w = fmaxf(v.w, 0.f);
            }
            if (flags & F_NEG) { v.x = -v.x; v.y = -v.y; v.z = -v.z; v.w = -v.w; }
            *(float4*)(out + (px0 + col) * C + ch) = v;
            if (flags & F_STATS) *(float4*)&es[col * EST + ch4 * 4] = v;
        }
        if (flags & F_STATS) {
            __syncthreads();
            const int n = (int)(px0 / HW);
            const int slot = (int)((px0 - (long)n * HW) / BN);
            for (int ch = tid; ch < BM; ch += 256) {
                float s = 0.f, s2 = 0.f;
#pragma unroll 4
                for (int col = 0; col < BN; col++) {
                    float x = es[col * EST + ch];
                    s += x;
                    s2 += x * x;
                }
                long o = (((long)slot * 8 + n) * C + m0 + ch) * 2;
                partial[o] = s;
                partial[o + 1] = s2;
            }
        }
    }
}

// ===========================================================================
// Host side
// ===========================================================================
struct DevPtrs {
    float* pool;
    __nv_bfloat16 *thi, *tlo, *zhi, *zlo, *whi, *wlo;
    float *partial, *stats, *gm;
};

static void run_gemm(const __nv_bfloat16* ahi, const __nv_bfloat16* alo,
                     const __nv_bfloat16* xhi, const __nv_bfloat16* xlo,
                     const float* bias, float* out, float* partial,
                     float* yb, float* accb, __nv_bfloat16* thi, __nv_bfloat16* tlo,
                     int C, int H, int W, int flags, int stage, float dt) {
    long PX = 8L * H * W;
    if (C == 64) {
        hgemm_conv<64, 128, 2, 4><<<dim3((unsigned)(PX / 128), 1), 256, 49152>>>(
            ahi, alo, xhi, xlo, bias, out, partial, yb, accb, thi, tlo,
            C, H, W, 1, flags, stage, dt);
    } else if (C == 128) {
        hgemm_conv<128, 128, 2, 4><<<dim3((unsigned)(PX / 128), 1), 256, 67584>>>(
            ahi, alo, xhi, xlo, bias, out, partial, yb, accb, thi, tlo,
            C, H, W, 2, flags, stage, dt);
    } else {
        hgemm_conv<128, 64, 4, 2><<<dim3((unsigned)(PX / 64), 2), 256, 49152>>>(
            ahi, alo, xhi, xlo, bias, out, partial, yb, accb, thi, tlo,
            C, H, W, 3, flags, stage, dt);
    }
}

static void ode_block(DevPtrs& P, float* y, const float* Wb, const float* bb,
                      int C, int H, int W, float* z, float* acc) {
    const int Nimg = 8, nsteps = 4;
    const float dt = 1.0f / nsteps;
    const int K = 9 * C, HW = H * W;
    const int BN = (C == 256) ? 64 : 128;
    const int cpi = HW / BN;
    long wtot = 8L * C * K;
    wprep_kernel<<<(unsigned)((wtot + 255) / 256), 256>>>(Wb, P.whi, P.wlo, C);

    long ipi = (long)HW * C;

    for (int i = 0; i < nsteps; i++) {
        int j = (i + 1 < nsteps) ? i + 1 : nsteps - 1;
        for (int s = 1; s <= 4; s++) {
            int bank = (s == 4) ? j : i;
            const __nv_bfloat16* wf_hi = P.whi + (size_t)(bank * 2 + 0) * C * K;
            const __nv_bfloat16* wf_lo = P.wlo + (size_t)(bank * 2 + 0) * C * K;
            const __nv_bfloat16* wt_hi = P.whi + (size_t)(bank * 2 + 1) * C * K;
            const __nv_bfloat16* wt_lo = P.wlo + (size_t)(bank * 2 + 1) * C * K;
            const float* bs = bb + (size_t)bank * C;

            run_gemm(wf_hi, wf_lo, P.thi, P.tlo, bs, z, P.partial,
                     nullptr, nullptr, nullptr, nullptr,
                     C, H, W, F_BIAS | F_RELU | F_STATS, 0, dt);
            reduce2_direct<<<Nimg, 256>>>(P.partial, P.stats, C, HW, cpi, Nimg);
            apply_kernel<<<dim3(64, Nimg), 256>>>(z, P.stats, nullptr, P.zhi, P.zlo,
                                                  C, ipi, 0, 2);
            run_gemm(wt_hi, wt_lo, P.zhi, P.zlo, nullptr, z, nullptr,
                     y, acc, P.thi, P.tlo, C, H, W, F_RK, s, dt);
        }
    }
}

extern "C" void kernel_launch(void* const* d_in, const int* in_sizes, int n_in,
                              void* d_out, int out_size) {
    const float* x       = (const float*)d_in[0];
    const float* stem_w  = (const float*)d_in[1];
    const float* stem_b  = (const float*)d_in[2];
    const float* norm1_g = (const float*)d_in[3];
    const float* norm1_b = (const float*)d_in[4];
    const float* ode1_W  = (const float*)d_in[5];
    const float* ode1_b  = (const float*)d_in[6];
    const float* conn1_w = (const float*)d_in[7];
    const float* conn1_b = (const float*)d_in[8];
    const float* norm3_g = (const float*)d_in[9];
    const float* norm3_b = (const float*)d_in[10];
    const float* ode2_W  = (const float*)d_in[11];
    const float* ode2_b  = (const float*)d_in[12];
    const float* conn2_w = (const float*)d_in[13];
    const float* conn2_b = (const float*)d_in[14];
    const float* norm4_g = (const float*)d_in[15];
    const float* norm4_b = (const float*)d_in[16];
    const float* ode3_W  = (const float*)d_in[17];
    const float* ode3_b  = (const float*)d_in[18];
    const float* head_w  = (const float*)d_in[19];
    const float* head_b  = (const float*)d_in[20];
    float* out = (float*)d_out;

    cudaFuncSetAttribute(hgemm_conv<64, 128, 2, 4>,
                         cudaFuncAttributeMaxDynamicSharedMemorySize, 49152);
    cudaFuncSetAttribute(hgemm_conv<128, 128, 2, 4>,
                         cudaFuncAttributeMaxDynamicSharedMemorySize, 67584);
    cudaFuncSetAttribute(hgemm_conv<128, 64, 4, 2>,
                         cudaFuncAttributeMaxDynamicSharedMemorySize, 49152);
    cudaFuncSetAttribute(conv1x1_kernel<128>,
                         cudaFuncAttributeMaxDynamicSharedMemorySize,
                         (64 * 128 + 65 * 128) * 4);

    DevPtrs P;
    cudaGetSymbolAddress((void**)&P.pool, g_pool);
    __nv_bfloat16* bhi;
    __nv_bfloat16* blo;
    cudaGetSymbolAddress((void**)&bhi, g_bhi);
    cudaGetSymbolAddress((void**)&blo, g_blo);
    P.thi = bhi;
    P.tlo = blo;
    P.zhi = bhi + 16777216ull;
    P.zlo = blo + 16777216ull;
    cudaGetSymbolAddress((void**)&P.whi, g_whi);
    cudaGetSymbolAddress((void**)&P.wlo, g_wlo);
    cudaGetSymbolAddress((void**)&P.partial, g_partial);
    cudaGetSymbolAddress((void**)&P.stats, g_stats);
    cudaGetSymbolAddress((void**)&P.gm, g_gm);

    float* A   = P.pool;                      // y
    float* KB  = P.pool + 2ull * SLOT_ELEMS;  // conn temp
    float* Z   = P.pool + 3ull * SLOT_ELEMS;  // z
    float* ACC = P.pool + 4ull * SLOT_ELEMS;

    const int N = 8;

    // ---- Stem
    stem_conv_kernel<<<dim3(9, 16, N), dim3(16, 16)>>>(x, stem_w, stem_b, Z, 3, 64, 96, 96, 3);
    stats_kernel<<<dim3(8, N), 256>>>(Z, P.partial, 64, 9216, N);
    reduce2_chunks<<<N, 256>>>(P.partial, norm1_g, norm1_b, P.stats, 64, N, 9216);
    apply_kernel<<<dim3(64, N), 256>>>(Z, P.stats, A, P.thi, P.tlo, 64, 9216L * 64, 1, 3);

    // ---- ODE block 1
    ode_block(P, A, ode1_W, ode1_b, 64, 96, 96, Z, ACC);

    // ---- conn1
    {
        long PX = (long)N * 9216;
        conv1x1_kernel<64><<<dim3((unsigned)(PX / 64), 2), 256, (64 * 64 + 65 * 64) * 4>>>(
            A, conn1_w, conn1_b, KB, 128);
        stats_kernel<<<dim3(8, N), 256>>>(KB, P.partial, 128, 9216, N);
        reduce2_chunks<<<N, 256>>>(P.partial, norm3_g, norm3_b, P.stats, 128, N, 9216);
        apply_kernel<<<dim3(64, N), 256>>>(KB, P.stats, Z, P.thi, P.tlo, 128, 9216L * 128, 1, 1);
        long total4 = (long)N * 48 * 48 * 128 / 4;
        avgpool2_kernel<<<(unsigned)((total4 + 255) / 256), 256>>>(Z, A, total4, 48, 48, 128);
        split_kernel<<<(unsigned)((total4 + 255) / 256), 256>>>((float4*)A, P.thi, P.tlo, total4);
    }

    // ---- ODE block 2
    ode_block(P, A, ode2_W, ode2_b, 128, 48, 48, Z, ACC);

    // ---- conn2
    {
        long PX = (long)N * 2304;
        conv1x1_kernel<128><<<dim3((unsigned)(PX / 64), 4), 256, (64 * 128 + 65 * 128) * 4>>>(
            A, conn2_w, conn2_b, KB, 256);
        stats_kernel<<<dim3(8, N), 256>>>(KB, P.partial, 256, 2304, N);
        reduce2_chunks<<<N, 256>>>(P.partial, norm4_g, norm4_b, P.stats, 256, N, 2304);
        apply_kernel<<<dim3(64, N), 256>>>(KB, P.stats, Z, P.thi, P.tlo, 256, 2304L * 256, 1, 1);
        long total4 = (long)N * 24 * 24 * 256 / 4;
        avgpool2_kernel<<<(unsigned)((total4 + 255) / 256), 256>>>(Z, A, total4, 24, 24, 256);
        split_kernel<<<(unsigned)((total4 + 255) / 256), 256>>>((float4*)A, P.thi, P.tlo, total4);
    }

    // ---- ODE block 3
    ode_block(P, A, ode3_W, ode3_b, 256, 24, 24, Z, ACC);

    // ---- Global mean + head
    gmean_kernel<<<N, 256>>>(A, P.gm, 576, 256);
    head_kernel<<<dim3(10, N), 256>>>(P.gm, head_w, head_b, out, 256);
}